// round 1
// baseline (speedup 1.0000x reference)
#include <cuda_runtime.h>
#include <cstdint>

// ---------------- problem constants (fixed shapes) ----------------
#define N_IMG   8
#define K_ANC   9
#define HH      120
#define WW      120
#define M_GT    64
#define A_ANCH  (HH*WW*K_ANC)      /* 129600 */
#define HALF_A  (A_ANCH/2)         /* 64800  */
#define HWSZ    (HH*WW)            /* 14400  */
#define IMG_SZ  1920.0f
#define KPOS    128
#define KNEG    60

// JAX threefry counter scheme: 1 = partitionable (new default), 0 = original
#define PARTITIONABLE 1

// ---------------- static device scratch (no allocations) ----------------
__device__ int      g_match[N_IMG*A_ANCH];
__device__ unsigned g_upos [N_IMG*A_ANCH];
__device__ unsigned g_uneg [N_IMG*A_ANCH];
__device__ uint2    g_sel  [N_IMG*2];      // x = threshold bits, y = #ties to take
__device__ float    g_acc  [N_IMG][5];     // bce, pred, l1, npos, nneg
__device__ int      g_eqc  [N_IMG][2];
__device__ int      g_eq   [N_IMG][2][64];

struct Keys { unsigned kp0[N_IMG], kp1[N_IMG], kn0[N_IMG], kn1[N_IMG]; };

// ---------------- threefry2x32 (JAX-exact) ----------------
__host__ __device__ __forceinline__ unsigned rotl32(unsigned x, int d) {
    return (x << d) | (x >> (32 - d));
}
__host__ __device__ __forceinline__ void tf2x32(unsigned k0, unsigned k1,
                                                unsigned x0, unsigned x1,
                                                unsigned& o0, unsigned& o1) {
    unsigned ks2 = k0 ^ k1 ^ 0x1BD11BDAu;
    x0 += k0; x1 += k1;
#define TFR(r) { x0 += x1; x1 = rotl32(x1, r); x1 ^= x0; }
    TFR(13) TFR(15) TFR(26) TFR(6)   x0 += k1;  x1 += ks2 + 1u;
    TFR(17) TFR(29) TFR(16) TFR(24)  x0 += ks2; x1 += k0  + 2u;
    TFR(13) TFR(15) TFR(26) TFR(6)   x0 += k0;  x1 += k1  + 3u;
    TFR(17) TFR(29) TFR(16) TFR(24)  x0 += k1;  x1 += ks2 + 4u;
    TFR(13) TFR(15) TFR(26) TFR(6)   x0 += ks2; x1 += k0  + 5u;
#undef TFR
    o0 = x0; o1 = x1;
}

// uniform(key)[i] as float bit pattern (0 means "u == 0.0 -> excluded")
__device__ __forceinline__ unsigned ubits(unsigned k0, unsigned k1, int i) {
    unsigned o0, o1, b;
#if PARTITIONABLE
    tf2x32(k0, k1, 0u, (unsigned)i, o0, o1);
    b = o0 ^ o1;
#else
    if (i < HALF_A) { tf2x32(k0, k1, (unsigned)i,            (unsigned)(i+HALF_A), o0, o1); b = o0; }
    else            { tf2x32(k0, k1, (unsigned)(i - HALF_A), (unsigned)i,          o0, o1); b = o1; }
#endif
    float u = __uint_as_float((b >> 9) | 0x3f800000u) - 1.0f;   // [0,1)
    return __float_as_uint(u);
}

// ---------------- geometry helpers ----------------
__device__ __forceinline__ void anchor_box(int a, int& k, int& h, int& w,
                                           float& ax1, float& ay1, float& ax2, float& ay2) {
    k = a % K_ANC; int hw = a / K_ANC; w = hw % WW; h = hw / WW;
    int r = k / 3, s = k % 3;
    float scale = (s == 0) ? 8.0f : ((s == 1) ? 16.0f : 32.0f);
    float sq2 = sqrtf(2.0f), sqh = sqrtf(0.5f);
    float srw = (r == 0) ? sq2 : ((r == 1) ? 1.0f : sqh);   // sqrt(1/ratio)
    float srh = (r == 0) ? sqh : ((r == 1) ? 1.0f : sq2);   // sqrt(ratio)
    float wsz = __fmul_rn(16.0f * scale, srw);
    float hsz = __fmul_rn(16.0f * scale, srh);
    float cx = __fmul_rn((float)w + 0.5f, 16.0f);
    float cy = __fmul_rn((float)h + 0.5f, 16.0f);
    float hw2 = __fmul_rn(wsz, 0.5f), hh2 = __fmul_rn(hsz, 0.5f);
    ax1 = __fsub_rn(cx, hw2); ay1 = __fsub_rn(cy, hh2);
    ax2 = __fadd_rn(cx, hw2); ay2 = __fadd_rn(cy, hh2);
}

__device__ __forceinline__ void region_box(const float* __restrict__ deltas,
                                           int n, int k, int h, int w,
                                           float ax1, float ay1, float ax2, float ay2,
                                           float& rx1, float& ry1, float& rx2, float& ry2) {
    int db = ((n * 4 * K_ANC + k * 4) * HH + h) * WW + w;
    rx1 = fminf(fmaxf(__fadd_rn(ax1, deltas[db          ]), 0.0f), IMG_SZ);
    ry1 = fminf(fmaxf(__fadd_rn(ay1, deltas[db +   HWSZ ]), 0.0f), IMG_SZ);
    rx2 = fminf(fmaxf(__fadd_rn(ax2, deltas[db + 2*HWSZ ]), 0.0f), IMG_SZ);
    ry2 = fminf(fmaxf(__fadd_rn(ay2, deltas[db + 3*HWSZ ]), 0.0f), IMG_SZ);
}

__device__ __forceinline__ int cls_index(int n, int a) {
    int k = a % K_ANC; int hw = a / K_ANC; int w = hw % WW; int h = hw / WW;
    return ((n * K_ANC + k) * HH + h) * WW + w;
}

__device__ __forceinline__ float softplusf(float x) {
    return fmaxf(x, 0.0f) + log1pf(expf(-fabsf(x)));
}
__device__ __forceinline__ float sl1(float d) {
    float ad = fabsf(d);
    return (ad < 0.1f) ? (0.5f * d * d / 0.1f) : (ad - 0.05f);
}

// contribution of one selected positive anchor
__device__ void pos_contrib(const float* __restrict__ cls, const float* __restrict__ deltas,
                            const float* __restrict__ gt, int n, int a,
                            float& bce, float& pred, float& l1) {
    int m = g_match[n * A_ANCH + a];
    if (m < 0) m = 0;
    int k, h, w; float ax1, ay1, ax2, ay2;
    anchor_box(a, k, h, w, ax1, ay1, ax2, ay2);
    float rx1, ry1, rx2, ry2;
    region_box(deltas, n, k, h, w, ax1, ay1, ax2, ay2, rx1, ry1, rx2, ry2);
    float aw = __fsub_rn(ax2, ax1), ah = __fsub_rn(ay2, ay1);
    float acx = ax1 + 0.5f * aw, acy = ay1 + 0.5f * ah;
    float bw = fmaxf(__fsub_rn(rx2, rx1), 1e-6f), bh = fmaxf(__fsub_rn(ry2, ry1), 1e-6f);
    float bcx = rx1 + 0.5f * bw, bcy = ry1 + 0.5f * bh;
    float tp0 = (bcx - acx) / aw, tp1 = (bcy - acy) / ah;
    float tp2 = logf(bw / aw),    tp3 = logf(bh / ah);
    const float* g = gt + (n * M_GT + m) * 4;
    float gw = fmaxf(__fsub_rn(g[2], g[0]), 1e-6f), gh = fmaxf(__fsub_rn(g[3], g[1]), 1e-6f);
    float gcx = g[0] + 0.5f * gw, gcy = g[1] + 0.5f * gh;
    float tg0 = (gcx - acx) / aw, tg1 = (gcy - acy) / ah;
    float tg2 = logf(gw / aw),    tg3 = logf(gh / ah);
    l1 += sl1(tp0 - tg0) + sl1(tp1 - tg1) + sl1(tp2 - tg2) + sl1(tp3 - tg3);
    float x = cls[((n * K_ANC + k) * HH + h) * WW + w];
    bce += softplusf(-x); pred += x;
}

// ---------------- kernel 0: zero scratch + output ----------------
__global__ void k_zero(float* out, int out_size) {
    int t = threadIdx.x;
    for (int i = t; i < out_size; i += blockDim.x) out[i] = 0.0f;
    if (t < N_IMG) {
        for (int j = 0; j < 5; j++) g_acc[t][j] = 0.0f;
        g_eqc[t][0] = 0; g_eqc[t][1] = 0;
    }
}

// ---------------- kernel 1: region + IoU match + uniform bits ----------------
__global__ void k_match(const float* __restrict__ cls, const float* __restrict__ deltas,
                        const float* __restrict__ gt, Keys keys) {
    int n = blockIdx.y;
    __shared__ float sg[M_GT * 4];
    __shared__ float sag[M_GT];
    for (int i = threadIdx.x; i < M_GT * 4; i += blockDim.x) sg[i] = gt[n * M_GT * 4 + i];
    __syncthreads();
    if (threadIdx.x < M_GT) {
        int m = threadIdx.x;
        sag[m] = __fmul_rn(fmaxf(__fsub_rn(sg[4*m+2], sg[4*m+0]), 0.0f),
                           fmaxf(__fsub_rn(sg[4*m+3], sg[4*m+1]), 0.0f));
    }
    __syncthreads();
    int a = blockIdx.x * blockDim.x + threadIdx.x;
    if (a >= A_ANCH) return;

    int k, h, w; float ax1, ay1, ax2, ay2;
    anchor_box(a, k, h, w, ax1, ay1, ax2, ay2);
    float rx1, ry1, rx2, ry2;
    region_box(deltas, n, k, h, w, ax1, ay1, ax2, ay2, rx1, ry1, rx2, ry2);
    float ab = __fmul_rn(fmaxf(__fsub_rn(rx2, rx1), 0.0f),
                         fmaxf(__fsub_rn(ry2, ry1), 0.0f));
    float best = -1.0f; int arg = 0;
#pragma unroll 4
    for (int m = 0; m < M_GT; m++) {
        float gx1 = sg[4*m], gy1 = sg[4*m+1], gx2 = sg[4*m+2], gy2 = sg[4*m+3];
        float ix1 = fmaxf(rx1, gx1), iy1 = fmaxf(ry1, gy1);
        float ix2 = fminf(rx2, gx2), iy2 = fminf(ry2, gy2);
        float inter = __fmul_rn(fmaxf(__fsub_rn(ix2, ix1), 0.0f),
                                fmaxf(__fsub_rn(iy2, iy1), 0.0f));
        float den = __fadd_rn(__fsub_rn(__fadd_rn(ab, sag[m]), inter), 1e-6f);
        float iou = __fdiv_rn(inter, den);
        if (iou > best) { best = iou; arg = m; }
    }
    int match = (best >= 0.4f) ? arg : ((best < 0.1f) ? -1 : -2);
    unsigned up = 0u, un = 0u;
    if (match >= 0)       up = ubits(keys.kp0[n], keys.kp1[n], a);
    else if (match == -1) un = ubits(keys.kn0[n], keys.kn1[n], a);
    int gidx = n * A_ANCH + a;
    g_match[gidx] = match; g_upos[gidx] = up; g_uneg[gidx] = un;
}

// ---------------- kernel 2: exact k-th largest via 4-pass radix select ----------------
__global__ void k_select() {
    int n = blockIdx.x, t = blockIdx.y;
    const unsigned* vals = (t == 0 ? g_upos : g_uneg) + n * A_ANCH;
    int K = (t == 0) ? KPOS : KNEG;
    __shared__ unsigned hist[256];
    __shared__ unsigned sprefix;
    __shared__ int sneed, sdone;
    if (threadIdx.x == 0) { sprefix = 0u; sneed = K; sdone = 0; }
    __syncthreads();
    for (int pass = 0; pass < 4; pass++) {
        for (int b = threadIdx.x; b < 256; b += blockDim.x) hist[b] = 0u;
        __syncthreads();
        if (!sdone) {
            int shift = 24 - pass * 8;
            unsigned pref = sprefix;
            for (int i = threadIdx.x; i < A_ANCH; i += blockDim.x) {
                unsigned v = vals[i];
                if (v == 0u) continue;
                if (pass > 0 && (v >> (shift + 8)) != pref) continue;
                atomicAdd(&hist[(v >> shift) & 0xFFu], 1u);
            }
        }
        __syncthreads();
        if (threadIdx.x == 0 && !sdone) {
            unsigned cum = 0; int selb = -1; int need = sneed;
            for (int b = 255; b >= 0; b--) {
                if (cum + hist[b] >= (unsigned)need) { selb = b; break; }
                cum += hist[b];
            }
            if (selb < 0) { sdone = 1; }  // total candidates < K -> take all (>0)
            else { sneed = need - (int)cum; sprefix = (sprefix << 8) | (unsigned)selb; }
        }
        __syncthreads();
    }
    if (threadIdx.x == 0) {
        unsigned T; unsigned r;
        if (sdone) { T = 0u; r = 0u; } else { T = sprefix; r = (unsigned)sneed; }
        g_sel[n * 2 + t] = make_uint2(T, r);
    }
}

// ---------------- kernel 3: masked reduction of selected samples ----------------
__global__ void k_reduce(const float* __restrict__ cls, const float* __restrict__ deltas,
                         const float* __restrict__ gt) {
    int n = blockIdx.y;
    uint2 sp = g_sel[2 * n], sn = g_sel[2 * n + 1];
    float bce = 0.f, pred = 0.f, l1 = 0.f, np = 0.f, nn = 0.f;
    int stride = gridDim.x * blockDim.x;
    for (int a = blockIdx.x * blockDim.x + threadIdx.x; a < A_ANCH; a += stride) {
        int gidx = n * A_ANCH + a;
        unsigned vp = g_upos[gidx];
        if (vp) {
            if (vp > sp.x) { pos_contrib(cls, deltas, gt, n, a, bce, pred, l1); np += 1.f; }
            else if (vp == sp.x && sp.x != 0u) {
                int c = atomicAdd(&g_eqc[n][0], 1);
                if (c < 64) g_eq[n][0][c] = a;
            }
        }
        unsigned vn = g_uneg[gidx];
        if (vn) {
            if (vn > sn.x) {
                float x = cls[cls_index(n, a)];
                bce += softplusf(x); pred += x; nn += 1.f;
            } else if (vn == sn.x && sn.x != 0u) {
                int c = atomicAdd(&g_eqc[n][1], 1);
                if (c < 64) g_eq[n][1][c] = a;
            }
        }
    }
#pragma unroll
    for (int o = 16; o > 0; o >>= 1) {
        bce  += __shfl_down_sync(0xffffffffu, bce,  o);
        pred += __shfl_down_sync(0xffffffffu, pred, o);
        l1   += __shfl_down_sync(0xffffffffu, l1,   o);
        np   += __shfl_down_sync(0xffffffffu, np,   o);
        nn   += __shfl_down_sync(0xffffffffu, nn,   o);
    }
    if ((threadIdx.x & 31) == 0) {
        atomicAdd(&g_acc[n][0], bce);
        atomicAdd(&g_acc[n][1], pred);
        atomicAdd(&g_acc[n][2], l1);
        atomicAdd(&g_acc[n][3], np);
        atomicAdd(&g_acc[n][4], nn);
    }
}

// ---------------- kernel 4: tie handling + per-image finalize ----------------
__global__ void k_final(const float* __restrict__ cls, const float* __restrict__ deltas,
                        const float* __restrict__ gt, float* out) {
    int n = blockIdx.x;
    if (threadIdx.x != 0) return;
    uint2 sp = g_sel[2 * n], sn = g_sel[2 * n + 1];
    float bce = g_acc[n][0], pred = g_acc[n][1], l1 = g_acc[n][2];
    float np = g_acc[n][3], nn = g_acc[n][4];
    int idx[64];
    // positive ties: take lowest-index r of them (lax.top_k tie rule)
    {
        int c = min(g_eqc[n][0], 64);
        for (int i = 0; i < c; i++) idx[i] = g_eq[n][0][i];
        for (int i = 1; i < c; i++) {
            int key = idx[i], j = i - 1;
            while (j >= 0 && idx[j] > key) { idx[j + 1] = idx[j]; j--; }
            idx[j + 1] = key;
        }
        int take = min((int)sp.y, c);
        for (int j = 0; j < take; j++) {
            pos_contrib(cls, deltas, gt, n, idx[j], bce, pred, l1);
            np += 1.f;
        }
    }
    // negative ties
    {
        int c = min(g_eqc[n][1], 64);
        for (int i = 0; i < c; i++) idx[i] = g_eq[n][1][i];
        for (int i = 1; i < c; i++) {
            int key = idx[i], j = i - 1;
            while (j >= 0 && idx[j] > key) { idx[j + 1] = idx[j]; j--; }
            idx[j + 1] = key;
        }
        int take = min((int)sn.y, c);
        for (int j = 0; j < take; j++) {
            float x = cls[cls_index(n, idx[j])];
            bce += softplusf(x); pred += x; nn += 1.f;
        }
    }
    float denom = fmaxf(np + nn, 1.0f);
    float cls_loss  = bce / denom;
    float bbox_loss = l1 / (fmaxf(np, 1.0f) * (float)N_IMG);
    atomicAdd(&out[0], cls_loss);
    atomicAdd(&out[1], bbox_loss);
    atomicAdd(&out[2], nn);       // bg.sum()
    atomicAdd(&out[3], np);       // fg.sum()
    if (n == N_IMG - 1) out[4] = pred / denom;   // pm[-1]
}

// ---------------- host launcher ----------------
extern "C" void kernel_launch(void* const* d_in, const int* in_sizes, int n_in,
                              void* d_out, int out_size) {
    (void)in_sizes; (void)n_in;
    const float* cls    = (const float*)d_in[0];
    const float* deltas = (const float*)d_in[1];
    const float* gt     = (const float*)d_in[2];
    float* out = (float*)d_out;

    // derive per-image (kp, kn) keys exactly as JAX does
    Keys keys;
#if PARTITIONABLE
    for (int n = 0; n < N_IMG; n++) {
        unsigned K0, K1;
        tf2x32(0u, 42u, 0u, (unsigned)n, K0, K1);          // key_n = tf(root, (0, n))
        unsigned p0, p1, q0, q1;
        tf2x32(K0, K1, 0u, 0u, p0, p1);                    // kp = tf(key_n, (0, 0))
        tf2x32(K0, K1, 0u, 1u, q0, q1);                    // kn = tf(key_n, (0, 1))
        keys.kp0[n] = p0; keys.kp1[n] = p1;
        keys.kn0[n] = q0; keys.kn1[n] = q1;
    }
#else
    unsigned w0[8], w1[8];
    for (int j = 0; j < 8; j++) tf2x32(0u, 42u, (unsigned)j, (unsigned)(j + 8), w0[j], w1[j]);
    for (int n = 0; n < N_IMG; n++) {
        unsigned K0, K1;
        if (n < 4) { K0 = w0[2 * n];     K1 = w0[2 * n + 1]; }
        else       { K0 = w1[2*(n-4)];   K1 = w1[2*(n-4)+1]; }
        unsigned a0, b0, a1, b1;
        tf2x32(K0, K1, 0u, 2u, a0, b0);
        tf2x32(K0, K1, 1u, 3u, a1, b1);
        keys.kp0[n] = a0; keys.kp1[n] = a1;
        keys.kn0[n] = b0; keys.kn1[n] = b1;
    }
#endif

    k_zero<<<1, 256>>>(out, out_size);
    dim3 g1((A_ANCH + 255) / 256, N_IMG);
    k_match<<<g1, 256>>>(cls, deltas, gt, keys);
    k_select<<<dim3(N_IMG, 2), 1024>>>();
    k_reduce<<<dim3(16, N_IMG), 256>>>(cls, deltas, gt);
    k_final<<<N_IMG, 1>>>(cls, deltas, gt, out);
}

// round 2
// speedup vs baseline: 2.8416x; 2.8416x over previous
#include <cuda_runtime.h>
#include <cstdint>

// ---------------- problem constants (fixed shapes) ----------------
#define N_IMG   8
#define K_ANC   9
#define HH      120
#define WW      120
#define M_GT    64
#define A_ANCH  (HH*WW*K_ANC)      /* 129600 */
#define HWSZ    (HH*WW)            /* 14400  */
#define IMG_SZ  1920.0f
#define KPOS    128
#define KNEG    60
#define NR      10                  /* ladder rungs */
#define CAP     4096                /* survivor capacity in shared */

// ---------------- static device scratch (no allocations) ----------------
__device__ uint2  g_pos[N_IMG * A_ANCH];   // (ubits, a | m<<17)
__device__ uint2  g_neg[N_IMG * A_ANCH];   // (ubits, a)
__device__ int    g_cnt[N_IMG * 2];
__device__ float4 g_part[N_IMG][2];        // (bce, pred, l1, count)

struct Keys { unsigned kp0[N_IMG], kp1[N_IMG], kn0[N_IMG], kn1[N_IMG]; };

// ---------------- threefry2x32 (JAX-exact) ----------------
__host__ __device__ __forceinline__ unsigned rotl32(unsigned x, int d) {
    return (x << d) | (x >> (32 - d));
}
__host__ __device__ __forceinline__ void tf2x32(unsigned k0, unsigned k1,
                                                unsigned x0, unsigned x1,
                                                unsigned& o0, unsigned& o1) {
    unsigned ks2 = k0 ^ k1 ^ 0x1BD11BDAu;
    x0 += k0; x1 += k1;
#define TFR(r) { x0 += x1; x1 = rotl32(x1, r); x1 ^= x0; }
    TFR(13) TFR(15) TFR(26) TFR(6)   x0 += k1;  x1 += ks2 + 1u;
    TFR(17) TFR(29) TFR(16) TFR(24)  x0 += ks2; x1 += k0  + 2u;
    TFR(13) TFR(15) TFR(26) TFR(6)   x0 += k0;  x1 += k1  + 3u;
    TFR(17) TFR(29) TFR(16) TFR(24)  x0 += k1;  x1 += ks2 + 4u;
    TFR(13) TFR(15) TFR(26) TFR(6)   x0 += ks2; x1 += k0  + 5u;
#undef TFR
    o0 = x0; o1 = x1;
}

// uniform(key)[i] as float bit pattern (0 means "u == 0.0 -> excluded")
__device__ __forceinline__ unsigned ubits(unsigned k0, unsigned k1, int i) {
    unsigned o0, o1;
    tf2x32(k0, k1, 0u, (unsigned)i, o0, o1);          // partitionable threefry
    unsigned b = o0 ^ o1;
    float u = __uint_as_float((b >> 9) | 0x3f800000u) - 1.0f;   // [0,1)
    return __float_as_uint(u);
}

// ---------------- geometry helpers ----------------
__device__ __forceinline__ void anchor_box(int k, int h, int w,
                                           float& ax1, float& ay1, float& ax2, float& ay2) {
    int r = k / 3, s = k % 3;
    float scale = (s == 0) ? 8.0f : ((s == 1) ? 16.0f : 32.0f);
    float sq2 = sqrtf(2.0f), sqh = sqrtf(0.5f);
    float srw = (r == 0) ? sq2 : ((r == 1) ? 1.0f : sqh);   // sqrt(1/ratio)
    float srh = (r == 0) ? sqh : ((r == 1) ? 1.0f : sq2);   // sqrt(ratio)
    float wsz = __fmul_rn(16.0f * scale, srw);
    float hsz = __fmul_rn(16.0f * scale, srh);
    float cx = __fmul_rn((float)w + 0.5f, 16.0f);
    float cy = __fmul_rn((float)h + 0.5f, 16.0f);
    float hw2 = __fmul_rn(wsz, 0.5f), hh2 = __fmul_rn(hsz, 0.5f);
    ax1 = __fsub_rn(cx, hw2); ay1 = __fsub_rn(cy, hh2);
    ax2 = __fadd_rn(cx, hw2); ay2 = __fadd_rn(cy, hh2);
}

__device__ __forceinline__ void region_box(const float* __restrict__ deltas,
                                           int n, int k, int h, int w,
                                           float ax1, float ay1, float ax2, float ay2,
                                           float& rx1, float& ry1, float& rx2, float& ry2) {
    int db = ((n * 4 * K_ANC + k * 4) * HH + h) * WW + w;
    rx1 = fminf(fmaxf(__fadd_rn(ax1, deltas[db          ]), 0.0f), IMG_SZ);
    ry1 = fminf(fmaxf(__fadd_rn(ay1, deltas[db +   HWSZ ]), 0.0f), IMG_SZ);
    rx2 = fminf(fmaxf(__fadd_rn(ax2, deltas[db + 2*HWSZ ]), 0.0f), IMG_SZ);
    ry2 = fminf(fmaxf(__fadd_rn(ay2, deltas[db + 3*HWSZ ]), 0.0f), IMG_SZ);
}

__device__ __forceinline__ int cls_index(int n, int a) {
    int k = a % K_ANC; int hw = a / K_ANC; int w = hw % WW; int h = hw / WW;
    return ((n * K_ANC + k) * HH + h) * WW + w;
}

__device__ __forceinline__ float softplusf(float x) {
    return fmaxf(x, 0.0f) + log1pf(expf(-fabsf(x)));
}
__device__ __forceinline__ float sl1(float d) {
    float ad = fabsf(d);
    return (ad < 0.1f) ? (0.5f * d * d / 0.1f) : (ad - 0.05f);
}

// contribution of one selected positive anchor (m supplied directly)
__device__ void pos_contrib(const float* __restrict__ cls, const float* __restrict__ deltas,
                            const float* __restrict__ gt, int n, int a, int m,
                            float& bce, float& pred, float& l1) {
    int k = a % K_ANC; int hw = a / K_ANC; int w = hw % WW; int h = hw / WW;
    float ax1, ay1, ax2, ay2;
    anchor_box(k, h, w, ax1, ay1, ax2, ay2);
    float rx1, ry1, rx2, ry2;
    region_box(deltas, n, k, h, w, ax1, ay1, ax2, ay2, rx1, ry1, rx2, ry2);
    float aw = __fsub_rn(ax2, ax1), ah = __fsub_rn(ay2, ay1);
    float acx = ax1 + 0.5f * aw, acy = ay1 + 0.5f * ah;
    float bw = fmaxf(__fsub_rn(rx2, rx1), 1e-6f), bh = fmaxf(__fsub_rn(ry2, ry1), 1e-6f);
    float bcx = rx1 + 0.5f * bw, bcy = ry1 + 0.5f * bh;
    float tp0 = (bcx - acx) / aw, tp1 = (bcy - acy) / ah;
    float tp2 = logf(bw / aw),    tp3 = logf(bh / ah);
    const float* g = gt + (n * M_GT + m) * 4;
    float gw = fmaxf(__fsub_rn(g[2], g[0]), 1e-6f), gh = fmaxf(__fsub_rn(g[3], g[1]), 1e-6f);
    float gcx = g[0] + 0.5f * gw, gcy = g[1] + 0.5f * gh;
    float tg0 = (gcx - acx) / aw, tg1 = (gcy - acy) / ah;
    float tg2 = logf(gw / aw),    tg3 = logf(gh / ah);
    l1 += sl1(tp0 - tg0) + sl1(tp1 - tg1) + sl1(tp2 - tg2) + sl1(tp3 - tg3);
    float x = cls[((n * K_ANC + k) * HH + h) * WW + w];
    bce += softplusf(-x); pred += x;
}

// ---------------- kernel 0: zero counters + output ----------------
__global__ void k_zero(float* out, int out_size) {
    int t = threadIdx.x;
    for (int i = t; i < out_size; i += blockDim.x) out[i] = 0.0f;
    if (t < N_IMG * 2) g_cnt[t] = 0;
}

// ---------------- kernel 1: region + IoU match + candidate compaction ----------------
// thread mapping: t -> (k, h, w) with w fastest => coalesced deltas/cls, warp-uniform k
#define K1_THREADS 320
__global__ __launch_bounds__(K1_THREADS) void k_match(
        const float* __restrict__ cls, const float* __restrict__ deltas,
        const float* __restrict__ gt, Keys keys) {
    int n = blockIdx.y;
    __shared__ float4 sg4[M_GT];
    __shared__ float  sag[M_GT];
    __shared__ int    scnt[2];
    __shared__ int    sbase[2];
    __shared__ int    wboff[K1_THREADS / 32][2];
    int tid = threadIdx.x;
    if (tid < M_GT) {
        float4 b = reinterpret_cast<const float4*>(gt)[n * M_GT + tid];
        sg4[tid] = b;
        sag[tid] = __fmul_rn(fmaxf(__fsub_rn(b.z, b.x), 0.0f),
                             fmaxf(__fsub_rn(b.w, b.y), 0.0f));
    }
    if (tid < 2) scnt[tid] = 0;
    __syncthreads();

    int t = blockIdx.x * K1_THREADS + tid;         // < 129600 exactly
    int k = t / HWSZ; int hw = t % HWSZ; int h = hw / WW; int w = hw % WW;
    int a = hw * K_ANC + k;                        // reference anchor index

    float ax1, ay1, ax2, ay2;
    anchor_box(k, h, w, ax1, ay1, ax2, ay2);
    float rx1, ry1, rx2, ry2;
    region_box(deltas, n, k, h, w, ax1, ay1, ax2, ay2, rx1, ry1, rx2, ry2);
    float ab = __fmul_rn(fmaxf(__fsub_rn(rx2, rx1), 0.0f),
                         fmaxf(__fsub_rn(ry2, ry1), 0.0f));
    float best = 0.0f; int arg = 0;                // identical to argmax (iou>=0, first-tie)
    for (int m = 0; m < M_GT; m++) {
        float4 g = sg4[m];
        float ix1 = fmaxf(rx1, g.x), iy1 = fmaxf(ry1, g.y);
        float ix2 = fminf(rx2, g.z), iy2 = fminf(ry2, g.w);
        float inter = __fmul_rn(fmaxf(__fsub_rn(ix2, ix1), 0.0f),
                                fmaxf(__fsub_rn(iy2, iy1), 0.0f));
        if (__any_sync(0xffffffffu, inter > 0.0f)) {
            float den = __fadd_rn(__fsub_rn(__fadd_rn(ab, sag[m]), inter), 1e-6f);
            float iou = (inter > 0.0f) ? __fdiv_rn(inter, den) : 0.0f;
            if (iou > best) { best = iou; arg = m; }
        }
    }
    int match = (best >= 0.4f) ? arg : ((best < 0.1f) ? -1 : -2);
    unsigned ub = 0u;
    if (match >= 0)       ub = ubits(keys.kp0[n], keys.kp1[n], a);
    else if (match == -1) ub = ubits(keys.kn0[n], keys.kn1[n], a);
    bool isp = (match >= 0) && (ub != 0u);
    bool isn = (match == -1) && (ub != 0u);

    int wid = tid >> 5, lane = tid & 31;
    unsigned mp = __ballot_sync(0xffffffffu, isp);
    unsigned mn = __ballot_sync(0xffffffffu, isn);
    if (lane == 0) {
        wboff[wid][0] = atomicAdd(&scnt[0], __popc(mp));
        wboff[wid][1] = atomicAdd(&scnt[1], __popc(mn));
    }
    __syncthreads();
    if (tid == 0) {
        sbase[0] = atomicAdd(&g_cnt[n * 2 + 0], scnt[0]);
        sbase[1] = atomicAdd(&g_cnt[n * 2 + 1], scnt[1]);
    }
    __syncthreads();
    unsigned lm = (1u << lane) - 1u;
    if (isp) {
        int p = sbase[0] + wboff[wid][0] + __popc(mp & lm);
        g_pos[n * A_ANCH + p] = make_uint2(ub, (unsigned)a | ((unsigned)arg << 17));
    }
    if (isn) {
        int p = sbase[1] + wboff[wid][1] + __popc(mn & lm);
        g_neg[n * A_ANCH + p] = make_uint2(ub, (unsigned)a);
    }
}

// ---------------- kernel 2: per-(image,category) exact top-K + loss reduce ----------------
__device__ __forceinline__ bool pair_less(uint2 A, uint2 B) {
    // ascending by (value asc, index desc) => descending order gives (value desc, index asc)
    if (A.x != B.x) return A.x < B.x;
    return (A.y & 0x1FFFFu) > (B.y & 0x1FFFFu);
}

__global__ __launch_bounds__(1024) void k_select(
        const float* __restrict__ cls, const float* __restrict__ deltas,
        const float* __restrict__ gt) {
    int bx = blockIdx.x;
    int n = bx >> 1, cat = bx & 1;                 // cat 0 = pos, 1 = neg
    int tid = threadIdx.x;
    int wid = tid >> 5, lane = tid & 31;
    const uint2* list = (cat ? g_neg : g_pos) + n * A_ANCH;
    int C = g_cnt[n * 2 + cat];
    int K = cat ? KNEG : KPOS;
    int need = min(K, C);

    __shared__ unsigned sth[NR];
    __shared__ int stot[NR];
    __shared__ uint2 ss[CAP];
    __shared__ int   swarp[32];
    __shared__ float fwarp[32];
    __shared__ unsigned sT;
    __shared__ int sS, sLo, sHi, sFlag;

    if (tid == 0) {
        float invC = 1.0f / (float)max(C, 1);
        for (int j = 0; j < NR - 1; j++) {
            float u = 1.0f - (float)((2 << j) * K) * invC;
            sth[j] = (u <= 0.0f) ? 1u : __float_as_uint(u);
        }
        sth[NR - 1] = 1u;                          // all candidates (values are > 0)
    }
    __syncthreads();

    // ---- ladder counting (no atomics) ----
    int cnt[NR];
#pragma unroll
    for (int j = 0; j < NR; j++) cnt[j] = 0;
    for (int i = tid; i < C; i += 1024) {
        unsigned v = list[i].x;
#pragma unroll
        for (int j = 0; j < NR; j++) cnt[j] += (v >= sth[j]);
    }
    for (int j = 0; j < NR; j++) {
        int r = cnt[j];
#pragma unroll
        for (int o = 16; o > 0; o >>= 1) r += __shfl_down_sync(0xffffffffu, r, o);
        if (lane == 0) swarp[wid] = r;
        __syncthreads();
        if (tid == 0) {
            int s = 0;
            for (int q = 0; q < 32; q++) s += swarp[q];
            stot[j] = s;
        }
        __syncthreads();
    }
    if (tid == 0) {
        int rung = NR - 1;
        for (int j = 0; j < NR; j++) if (stot[j] >= need) { rung = j; break; }
        sT = sth[rung]; sS = stot[rung];
        sLo = (int)rung; sHi = 0;
        sFlag = (stot[rung] > CAP) ? 1 : 0;
    }
    __syncthreads();

    // ---- deterministic fallback: binary search for tightest threshold (rare) ----
    while (sFlag) {
        __syncthreads();
        if (tid == 0) {
            int rung = sLo;
            unsigned lo = sth[rung];
            unsigned hi = (rung > 0) ? sth[rung - 1] : 0xFFFFFFFFu;
            sLo = (int)lo; sHi = (int)hi;
        }
        __syncthreads();
        for (int iter = 0; iter < 34; iter++) {
            unsigned lo = (unsigned)sLo, hi = (unsigned)sHi;
            if (hi - lo <= 1u) break;
            unsigned mid = lo + ((hi - lo) >> 1);
            int c = 0;
            for (int i = tid; i < C; i += 1024) c += (list[i].x >= mid);
#pragma unroll
            for (int o = 16; o > 0; o >>= 1) c += __shfl_down_sync(0xffffffffu, c, o);
            if (lane == 0) swarp[wid] = c;
            __syncthreads();
            if (tid == 0) {
                int s = 0;
                for (int q = 0; q < 32; q++) s += swarp[q];
                if (s >= need) { sLo = (int)mid; sT = mid; sS = s; }
                else           { sHi = (int)mid; }
            }
            __syncthreads();
        }
        if (tid == 0) sFlag = 0;
        __syncthreads();
    }

    unsigned T = sT;
    int S = min(sS, CAP);

    // ---- compact survivors into shared via block prefix scan ----
    int my = 0;
    for (int i = tid; i < C; i += 1024) my += (list[i].x >= T);
    int incl = my;
#pragma unroll
    for (int o = 1; o < 32; o <<= 1) {
        int v = __shfl_up_sync(0xffffffffu, incl, o);
        if (lane >= o) incl += v;
    }
    if (lane == 31) swarp[wid] = incl;
    __syncthreads();
    if (tid == 0) {
        int run = 0;
        for (int q = 0; q < 32; q++) { int v = swarp[q]; swarp[q] = run; run += v; }
    }
    __syncthreads();
    int off = swarp[wid] + incl - my;
    for (int i = tid; i < C; i += 1024) {
        uint2 e = list[i];
        if (e.x >= T) { if (off < CAP) ss[off] = e; off++; }
    }

    // ---- pad + bitonic sort ascending (value asc, index desc) ----
    int Npow = 1; while (Npow < S) Npow <<= 1;
    if (Npow < 1) Npow = 1;
    for (int i = S + tid; i < Npow; i += 1024) ss[i] = make_uint2(0u, 0x1FFFFu);
    __syncthreads();
    for (unsigned sz = 2; sz <= (unsigned)Npow; sz <<= 1) {
        for (unsigned st = sz >> 1; st > 0; st >>= 1) {
            for (int i = tid; i < Npow; i += 1024) {
                int j = i ^ (int)st;
                if (j > i) {
                    uint2 A = ss[i], B = ss[j];
                    bool up = ((i & sz) == 0);
                    bool sw = up ? pair_less(B, A) : pair_less(A, B);
                    if (sw) { ss[i] = B; ss[j] = A; }
                }
            }
            __syncthreads();
        }
    }

    // ---- accumulate loss contributions of the top `need` ----
    float b = 0.0f, p = 0.0f, l = 0.0f;
    if (tid < need) {
        uint2 e = ss[Npow - 1 - tid];              // descending order
        int a = (int)(e.y & 0x1FFFFu);
        if (cat) {
            float x = cls[cls_index(n, a)];
            b = softplusf(x); p = x;
        } else {
            int m = (int)(e.y >> 17);
            pos_contrib(cls, deltas, gt, n, a, m, b, p, l);
        }
    }
    // block reduce b, p, l
    float vals[3] = {b, p, l};
    float out3[3];
    for (int q = 0; q < 3; q++) {
        float v = vals[q];
#pragma unroll
        for (int o = 16; o > 0; o >>= 1) v += __shfl_down_sync(0xffffffffu, v, o);
        if (lane == 0) fwarp[wid] = v;
        __syncthreads();
        if (tid == 0) {
            float s = 0.0f;
            for (int w2 = 0; w2 < 32; w2++) s += fwarp[w2];
            out3[q] = s;
        }
        __syncthreads();
    }
    if (tid == 0) g_part[n][cat] = make_float4(out3[0], out3[1], out3[2], (float)need);
}

// ---------------- kernel 3: finalize ----------------
__global__ void k_final(float* out) {
    if (threadIdx.x != 0 || blockIdx.x != 0) return;
    float cl = 0.f, bl = 0.f, fg = 0.f, bg = 0.f, pm = 0.f;
    for (int n = 0; n < N_IMG; n++) {
        float4 P = g_part[n][0];
        float4 G = g_part[n][1];
        float np = P.w, nn = G.w;
        float denom = fmaxf(np + nn, 1.0f);
        cl += (P.x + G.x) / denom;
        bl += P.z / (fmaxf(np, 1.0f) * (float)N_IMG);
        fg += np; bg += nn;
        if (n == N_IMG - 1) pm = (P.y + G.y) / denom;
    }
    out[0] = cl; out[1] = bl; out[2] = bg; out[3] = fg; out[4] = pm;
}

// ---------------- host launcher ----------------
extern "C" void kernel_launch(void* const* d_in, const int* in_sizes, int n_in,
                              void* d_out, int out_size) {
    (void)in_sizes; (void)n_in;
    const float* cls    = (const float*)d_in[0];
    const float* deltas = (const float*)d_in[1];
    const float* gt     = (const float*)d_in[2];
    float* out = (float*)d_out;

    Keys keys;
    for (int n = 0; n < N_IMG; n++) {
        unsigned K0, K1;
        tf2x32(0u, 42u, 0u, (unsigned)n, K0, K1);          // key_n = tf(root, (0, n))
        unsigned p0, p1, q0, q1;
        tf2x32(K0, K1, 0u, 0u, p0, p1);                    // kp
        tf2x32(K0, K1, 0u, 1u, q0, q1);                    // kn
        keys.kp0[n] = p0; keys.kp1[n] = p1;
        keys.kn0[n] = q0; keys.kn1[n] = q1;
    }

    k_zero<<<1, 256>>>(out, out_size);
    dim3 g1(A_ANCH / K1_THREADS, N_IMG);                   // 405 x 8
    k_match<<<g1, K1_THREADS>>>(cls, deltas, gt, keys);
    k_select<<<N_IMG * 2, 1024>>>(cls, deltas, gt);
    k_final<<<1, 32>>>(out);
}

// round 3
// speedup vs baseline: 4.2488x; 1.4952x over previous
#include <cuda_runtime.h>
#include <cstdint>

// ---------------- problem constants (fixed shapes) ----------------
#define N_IMG   8
#define K_ANC   9
#define HH      120
#define WW      120
#define M_GT    64
#define A_ANCH  (HH*WW*K_ANC)      /* 129600 */
#define HWSZ    (HH*WW)            /* 14400  */
#define IMG_SZ  1920.0f
#define KPOS    128
#define KNEG    60
#define NR      10                  /* ladder rungs */
#define CAP     4096                /* survivor capacity in shared */

// ---------------- static device scratch (no allocations) ----------------
__device__ uint2  g_pos[N_IMG * A_ANCH];   // (ubits, a | m<<17)
__device__ uint2  g_neg[N_IMG * A_ANCH];   // (ubits, a)
__device__ int    g_cnt[N_IMG * 2];        // zero-init; reset by k_select each run
__device__ float4 g_part[N_IMG][2];        // (bce, pred, l1, count)
__device__ int    g_ticket;                // zero-init; reset by last block

__constant__ float4 c_gt[N_IMG * M_GT];

struct Keys { unsigned kp0[N_IMG], kp1[N_IMG], kn0[N_IMG], kn1[N_IMG]; };

// ---------------- threefry2x32 (JAX-exact) ----------------
__host__ __device__ __forceinline__ unsigned rotl32(unsigned x, int d) {
    return (x << d) | (x >> (32 - d));
}
__host__ __device__ __forceinline__ void tf2x32(unsigned k0, unsigned k1,
                                                unsigned x0, unsigned x1,
                                                unsigned& o0, unsigned& o1) {
    unsigned ks2 = k0 ^ k1 ^ 0x1BD11BDAu;
    x0 += k0; x1 += k1;
#define TFR(r) { x0 += x1; x1 = rotl32(x1, r); x1 ^= x0; }
    TFR(13) TFR(15) TFR(26) TFR(6)   x0 += k1;  x1 += ks2 + 1u;
    TFR(17) TFR(29) TFR(16) TFR(24)  x0 += ks2; x1 += k0  + 2u;
    TFR(13) TFR(15) TFR(26) TFR(6)   x0 += k0;  x1 += k1  + 3u;
    TFR(17) TFR(29) TFR(16) TFR(24)  x0 += k1;  x1 += ks2 + 4u;
    TFR(13) TFR(15) TFR(26) TFR(6)   x0 += ks2; x1 += k0  + 5u;
#undef TFR
    o0 = x0; o1 = x1;
}

// uniform(key)[i] as float bit pattern (0 means "u == 0.0 -> excluded")
__device__ __forceinline__ unsigned ubits(unsigned k0, unsigned k1, int i) {
    unsigned o0, o1;
    tf2x32(k0, k1, 0u, (unsigned)i, o0, o1);          // partitionable threefry
    unsigned b = o0 ^ o1;
    float u = __uint_as_float((b >> 9) | 0x3f800000u) - 1.0f;   // [0,1)
    return __float_as_uint(u);
}

// ---------------- geometry helpers ----------------
__device__ __forceinline__ void anchor_box(int k, int h, int w,
                                           float& ax1, float& ay1, float& ax2, float& ay2) {
    int r = k / 3, s = k % 3;
    float scale = (s == 0) ? 8.0f : ((s == 1) ? 16.0f : 32.0f);
    float sq2 = sqrtf(2.0f), sqh = sqrtf(0.5f);
    float srw = (r == 0) ? sq2 : ((r == 1) ? 1.0f : sqh);   // sqrt(1/ratio)
    float srh = (r == 0) ? sqh : ((r == 1) ? 1.0f : sq2);   // sqrt(ratio)
    float wsz = __fmul_rn(16.0f * scale, srw);
    float hsz = __fmul_rn(16.0f * scale, srh);
    float cx = __fmul_rn((float)w + 0.5f, 16.0f);
    float cy = __fmul_rn((float)h + 0.5f, 16.0f);
    float hw2 = __fmul_rn(wsz, 0.5f), hh2 = __fmul_rn(hsz, 0.5f);
    ax1 = __fsub_rn(cx, hw2); ay1 = __fsub_rn(cy, hh2);
    ax2 = __fadd_rn(cx, hw2); ay2 = __fadd_rn(cy, hh2);
}

__device__ __forceinline__ void region_box(const float* __restrict__ deltas,
                                           int n, int k, int h, int w,
                                           float ax1, float ay1, float ax2, float ay2,
                                           float& rx1, float& ry1, float& rx2, float& ry2) {
    int db = ((n * 4 * K_ANC + k * 4) * HH + h) * WW + w;
    rx1 = fminf(fmaxf(__fadd_rn(ax1, deltas[db          ]), 0.0f), IMG_SZ);
    ry1 = fminf(fmaxf(__fadd_rn(ay1, deltas[db +   HWSZ ]), 0.0f), IMG_SZ);
    rx2 = fminf(fmaxf(__fadd_rn(ax2, deltas[db + 2*HWSZ ]), 0.0f), IMG_SZ);
    ry2 = fminf(fmaxf(__fadd_rn(ay2, deltas[db + 3*HWSZ ]), 0.0f), IMG_SZ);
}

__device__ __forceinline__ int cls_index(int n, int a) {
    int k = a % K_ANC; int hw = a / K_ANC; int w = hw % WW; int h = hw / WW;
    return ((n * K_ANC + k) * HH + h) * WW + w;
}

__device__ __forceinline__ float softplusf(float x) {
    return fmaxf(x, 0.0f) + log1pf(expf(-fabsf(x)));
}
__device__ __forceinline__ float sl1(float d) {
    float ad = fabsf(d);
    return (ad < 0.1f) ? (0.5f * d * d / 0.1f) : (ad - 0.05f);
}

// contribution of one selected positive anchor (m supplied directly)
__device__ void pos_contrib(const float* __restrict__ cls, const float* __restrict__ deltas,
                            const float* __restrict__ gt, int n, int a, int m,
                            float& bce, float& pred, float& l1) {
    int k = a % K_ANC; int hw = a / K_ANC; int w = hw % WW; int h = hw / WW;
    float ax1, ay1, ax2, ay2;
    anchor_box(k, h, w, ax1, ay1, ax2, ay2);
    float rx1, ry1, rx2, ry2;
    region_box(deltas, n, k, h, w, ax1, ay1, ax2, ay2, rx1, ry1, rx2, ry2);
    float aw = __fsub_rn(ax2, ax1), ah = __fsub_rn(ay2, ay1);
    float acx = ax1 + 0.5f * aw, acy = ay1 + 0.5f * ah;
    float bw = fmaxf(__fsub_rn(rx2, rx1), 1e-6f), bh = fmaxf(__fsub_rn(ry2, ry1), 1e-6f);
    float bcx = rx1 + 0.5f * bw, bcy = ry1 + 0.5f * bh;
    float tp0 = (bcx - acx) / aw, tp1 = (bcy - acy) / ah;
    float tp2 = logf(bw / aw),    tp3 = logf(bh / ah);
    const float* g = gt + (n * M_GT + m) * 4;
    float gw = fmaxf(__fsub_rn(g[2], g[0]), 1e-6f), gh = fmaxf(__fsub_rn(g[3], g[1]), 1e-6f);
    float gcx = g[0] + 0.5f * gw, gcy = g[1] + 0.5f * gh;
    float tg0 = (gcx - acx) / aw, tg1 = (gcy - acy) / ah;
    float tg2 = logf(gw / aw),    tg3 = logf(gh / ah);
    l1 += sl1(tp0 - tg0) + sl1(tp1 - tg1) + sl1(tp2 - tg2) + sl1(tp3 - tg3);
    float x = cls[((n * K_ANC + k) * HH + h) * WW + w];
    bce += softplusf(-x); pred += x;
}

// ---------------- kernel 1: region + IoU match + candidate compaction ----------------
// thread mapping: t -> (k, h, w) with w fastest => coalesced deltas, warp-uniform k
#define K1_THREADS 320
__global__ __launch_bounds__(K1_THREADS) void k_match(
        const float* __restrict__ deltas, Keys keys) {
    int n = blockIdx.y;
    __shared__ float  sag[M_GT];
    __shared__ int    scnt[2];
    __shared__ int    sbase[2];
    __shared__ int    wboff[K1_THREADS / 32][2];
    int tid = threadIdx.x;
    if (tid < M_GT) {
        float4 b = c_gt[n * M_GT + tid];
        sag[tid] = __fmul_rn(fmaxf(__fsub_rn(b.z, b.x), 0.0f),
                             fmaxf(__fsub_rn(b.w, b.y), 0.0f));
    }
    if (tid < 2) scnt[tid] = 0;
    __syncthreads();

    int t = blockIdx.x * K1_THREADS + tid;         // < 129600 exactly
    int k = t / HWSZ; int hw = t % HWSZ; int h = hw / WW; int w = hw % WW;
    int a = hw * K_ANC + k;                        // reference anchor index

    float ax1, ay1, ax2, ay2;
    anchor_box(k, h, w, ax1, ay1, ax2, ay2);
    float rx1, ry1, rx2, ry2;
    region_box(deltas, n, k, h, w, ax1, ay1, ax2, ay2, rx1, ry1, rx2, ry2);
    float ab = __fmul_rn(fmaxf(__fsub_rn(rx2, rx1), 0.0f),
                         fmaxf(__fsub_rn(ry2, ry1), 0.0f));
    float best = 0.0f; int arg = 0;                // identical to argmax (iou>=0, first-tie)
    const float4* gbase = &c_gt[n * M_GT];
#pragma unroll 8
    for (int m = 0; m < M_GT; m++) {
        float4 g = gbase[m];                       // uniform -> LDCU (const port)
        float ix1 = fmaxf(rx1, g.x), iy1 = fmaxf(ry1, g.y);
        float ix2 = fminf(rx2, g.z), iy2 = fminf(ry2, g.w);
        float inter = __fmul_rn(fmaxf(__fsub_rn(ix2, ix1), 0.0f),
                                fmaxf(__fsub_rn(iy2, iy1), 0.0f));
        float den = __fadd_rn(__fsub_rn(__fadd_rn(ab, sag[m]), inter), 1e-6f);
        // conservative screen: pass whenever fl(inter/den) could exceed best
        if (inter > __fmul_rn(__fmul_rn(best, den), 0.9999995f) && inter > 0.0f) {
            float iou = __fdiv_rn(inter, den);
            if (iou > best) { best = iou; arg = m; }
        }
    }
    int match = (best >= 0.4f) ? arg : ((best < 0.1f) ? -1 : -2);
    unsigned ub = 0u;
    if (match >= 0)       ub = ubits(keys.kp0[n], keys.kp1[n], a);
    else if (match == -1) ub = ubits(keys.kn0[n], keys.kn1[n], a);
    bool isp = (match >= 0) && (ub != 0u);
    bool isn = (match == -1) && (ub != 0u);

    int wid = tid >> 5, lane = tid & 31;
    unsigned mp = __ballot_sync(0xffffffffu, isp);
    unsigned mn = __ballot_sync(0xffffffffu, isn);
    if (lane == 0) {
        wboff[wid][0] = atomicAdd(&scnt[0], __popc(mp));
        wboff[wid][1] = atomicAdd(&scnt[1], __popc(mn));
    }
    __syncthreads();
    if (tid == 0) {
        sbase[0] = atomicAdd(&g_cnt[n * 2 + 0], scnt[0]);
        sbase[1] = atomicAdd(&g_cnt[n * 2 + 1], scnt[1]);
    }
    __syncthreads();
    unsigned lm = (1u << lane) - 1u;
    if (isp) {
        int p = sbase[0] + wboff[wid][0] + __popc(mp & lm);
        g_pos[n * A_ANCH + p] = make_uint2(ub, (unsigned)a | ((unsigned)arg << 17));
    }
    if (isn) {
        int p = sbase[1] + wboff[wid][1] + __popc(mn & lm);
        g_neg[n * A_ANCH + p] = make_uint2(ub, (unsigned)a);
    }
}

// ---------------- kernel 2: exact top-K + loss reduce + finalize (last block) ----------------
__device__ __forceinline__ bool pair_less(uint2 A, uint2 B) {
    // ascending by (value asc, index desc) => descending order gives (value desc, index asc)
    if (A.x != B.x) return A.x < B.x;
    return (A.y & 0x1FFFFu) > (B.y & 0x1FFFFu);
}

__global__ __launch_bounds__(1024) void k_select(
        const float* __restrict__ cls, const float* __restrict__ deltas,
        const float* __restrict__ gt, float* out, int out_size) {
    int bx = blockIdx.x;
    int n = bx >> 1, cat = bx & 1;                 // cat 0 = pos, 1 = neg
    int tid = threadIdx.x;
    int wid = tid >> 5, lane = tid & 31;
    const uint2* list = (cat ? g_neg : g_pos) + n * A_ANCH;
    int C = g_cnt[n * 2 + cat];
    if (tid == 0) g_cnt[n * 2 + cat] = 0;          // reset for next replay
    int K = cat ? KNEG : KPOS;
    int need = min(K, C);

    __shared__ unsigned sth[NR];
    __shared__ int stot[NR];
    __shared__ uint2 ss[CAP];
    __shared__ int   swarp[32];
    __shared__ float fwarp[32];
    __shared__ unsigned sT;
    __shared__ int sS, sLo, sHi, sFlag, scap;

    if (tid == 0) {
        float invC = 1.0f / (float)max(C, 1);
        for (int j = 0; j < NR - 1; j++) {
            float u = 1.0f - (float)((2 << j) * K) * invC;
            sth[j] = (u <= 0.0f) ? 1u : __float_as_uint(u);
        }
        sth[NR - 1] = 1u;                          // all candidates (values are > 0)
        scap = 0;
    }
    __syncthreads();

    // ---- single scan: ladder counts + opportunistic capture at rung 0 ----
    unsigned T0 = sth[0];
    int cnt[NR];
#pragma unroll
    for (int j = 0; j < NR; j++) cnt[j] = 0;
    for (int i = tid; i < C; i += 1024) {
        uint2 e = list[i];
        unsigned v = e.x;
#pragma unroll
        for (int j = 0; j < NR; j++) cnt[j] += (v >= sth[j]);
        if (v >= T0) {
            int p = atomicAdd(&scap, 1);
            if (p < CAP) ss[p] = e;                // order-free: sorted later
        }
    }
    for (int j = 0; j < NR; j++) {
        int r = cnt[j];
#pragma unroll
        for (int o = 16; o > 0; o >>= 1) r += __shfl_down_sync(0xffffffffu, r, o);
        if (lane == 0) swarp[wid] = r;
        __syncthreads();
        if (tid == 0) {
            int s = 0;
            for (int q = 0; q < 32; q++) s += swarp[q];
            stot[j] = s;
        }
        __syncthreads();
    }
    bool usable0 = (stot[0] >= need) && (stot[0] <= CAP);
    int S;
    if (usable0) {
        S = stot[0];
    } else {
        // ---- rare fallback: choose rung / binary-search threshold, then recapture ----
        if (tid == 0) {
            int rung = NR - 1;
            for (int j = 0; j < NR; j++) if (stot[j] >= need) { rung = j; break; }
            sT = sth[rung]; sS = stot[rung];
            sLo = rung;
            sFlag = (stot[rung] > CAP) ? 1 : 0;
        }
        __syncthreads();
        while (sFlag) {
            __syncthreads();
            if (tid == 0) {
                int rung = sLo;
                unsigned lo = sth[rung];
                unsigned hi = (rung > 0) ? sth[rung - 1] : 0xFFFFFFFFu;
                sLo = (int)lo; sHi = (int)hi;
            }
            __syncthreads();
            for (int iter = 0; iter < 34; iter++) {
                unsigned lo = (unsigned)sLo, hi = (unsigned)sHi;
                if (hi - lo <= 1u) break;
                unsigned mid = lo + ((hi - lo) >> 1);
                int c = 0;
                for (int i = tid; i < C; i += 1024) c += (list[i].x >= mid);
#pragma unroll
                for (int o = 16; o > 0; o >>= 1) c += __shfl_down_sync(0xffffffffu, c, o);
                if (lane == 0) swarp[wid] = c;
                __syncthreads();
                if (tid == 0) {
                    int s = 0;
                    for (int q = 0; q < 32; q++) s += swarp[q];
                    if (s >= need) { sLo = (int)mid; sT = mid; sS = s; }
                    else           { sHi = (int)mid; }
                }
                __syncthreads();
            }
            if (tid == 0) sFlag = 0;
            __syncthreads();
        }
        if (tid == 0) scap = 0;
        __syncthreads();
        unsigned T = sT;
        for (int i = tid; i < C; i += 1024) {
            uint2 e = list[i];
            if (e.x >= T) {
                int p = atomicAdd(&scap, 1);
                if (p < CAP) ss[p] = e;
            }
        }
        __syncthreads();
        S = min(sS, CAP);
    }
    __syncthreads();

    // ---- pad + bitonic sort ascending (value asc, index desc) ----
    int Npow = 1; while (Npow < S) Npow <<= 1;
    for (int i = S + tid; i < Npow; i += 1024) ss[i] = make_uint2(0u, 0x1FFFFu);
    __syncthreads();
    for (unsigned sz = 2; sz <= (unsigned)Npow; sz <<= 1) {
        for (unsigned st = sz >> 1; st > 0; st >>= 1) {
            for (int i = tid; i < Npow; i += 1024) {
                int j = i ^ (int)st;
                if (j > i) {
                    uint2 A = ss[i], B = ss[j];
                    bool up = ((i & sz) == 0);
                    bool sw = up ? pair_less(B, A) : pair_less(A, B);
                    if (sw) { ss[i] = B; ss[j] = A; }
                }
            }
            __syncthreads();
        }
    }

    // ---- accumulate loss contributions of the top `need` ----
    float b = 0.0f, p = 0.0f, l = 0.0f;
    if (tid < need) {
        uint2 e = ss[Npow - 1 - tid];              // descending order
        int a = (int)(e.y & 0x1FFFFu);
        if (cat) {
            float x = cls[cls_index(n, a)];
            b = softplusf(x); p = x;
        } else {
            int m = (int)(e.y >> 17);
            pos_contrib(cls, deltas, gt, n, a, m, b, p, l);
        }
    }
    float vals[3] = {b, p, l};
    float out3[3];
    for (int q = 0; q < 3; q++) {
        float v = vals[q];
#pragma unroll
        for (int o = 16; o > 0; o >>= 1) v += __shfl_down_sync(0xffffffffu, v, o);
        if (lane == 0) fwarp[wid] = v;
        __syncthreads();
        if (tid == 0) {
            float s = 0.0f;
            for (int w2 = 0; w2 < 32; w2++) s += fwarp[w2];
            out3[q] = s;
        }
        __syncthreads();
    }

    // ---- last block finalizes ----
    if (tid == 0) {
        g_part[n][cat] = make_float4(out3[0], out3[1], out3[2], (float)need);
        __threadfence();
        int ticket = atomicAdd(&g_ticket, 1);
        if (ticket == N_IMG * 2 - 1) {
            __threadfence();
            float cl = 0.f, bl = 0.f, fg = 0.f, bg = 0.f, pm = 0.f;
            for (int q = 0; q < N_IMG; q++) {
                volatile float* Pp = (volatile float*)&g_part[q][0];
                volatile float* Gg = (volatile float*)&g_part[q][1];
                float Pb = Pp[0], Pd = Pp[1], Pl = Pp[2], np = Pp[3];
                float Gb = Gg[0], Gd = Gg[1], nn = Gg[3];
                float denom = fmaxf(np + nn, 1.0f);
                cl += (Pb + Gb) / denom;
                bl += Pl / (fmaxf(np, 1.0f) * (float)N_IMG);
                fg += np; bg += nn;
                if (q == N_IMG - 1) pm = (Pd + Gd) / denom;
            }
            out[0] = cl; out[1] = bl; out[2] = bg; out[3] = fg; out[4] = pm;
            for (int i = 5; i < out_size; i++) out[i] = 0.0f;
            g_ticket = 0;                          // reset for next replay
        }
    }
}

// ---------------- host launcher ----------------
extern "C" void kernel_launch(void* const* d_in, const int* in_sizes, int n_in,
                              void* d_out, int out_size) {
    (void)in_sizes; (void)n_in;
    const float* cls    = (const float*)d_in[0];
    const float* deltas = (const float*)d_in[1];
    const float* gt     = (const float*)d_in[2];
    float* out = (float*)d_out;

    Keys keys;
    for (int n = 0; n < N_IMG; n++) {
        unsigned K0, K1;
        tf2x32(0u, 42u, 0u, (unsigned)n, K0, K1);          // key_n = tf(root, (0, n))
        unsigned p0, p1, q0, q1;
        tf2x32(K0, K1, 0u, 0u, p0, p1);                    // kp
        tf2x32(K0, K1, 0u, 1u, q0, q1);                    // kn
        keys.kp0[n] = p0; keys.kp1[n] = p1;
        keys.kn0[n] = q0; keys.kn1[n] = q1;
    }

    // GT boxes -> constant memory (D2D copy: graph-capturable)
    cudaMemcpyToSymbolAsync(c_gt, gt, N_IMG * M_GT * sizeof(float4), 0,
                            cudaMemcpyDeviceToDevice, 0);

    dim3 g1(A_ANCH / K1_THREADS, N_IMG);                   // 405 x 8
    k_match<<<g1, K1_THREADS>>>(deltas, keys);
    k_select<<<N_IMG * 2, 1024>>>(cls, deltas, gt, out, out_size);
}

// round 5
// speedup vs baseline: 4.5841x; 1.0789x over previous
#include <cuda_runtime.h>
#include <cstdint>

// ---------------- problem constants (fixed shapes) ----------------
#define N_IMG   8
#define K_ANC   9
#define HH      120
#define WW      120
#define M_GT    64
#define A_ANCH  (HH*WW*K_ANC)      /* 129600 */
#define HWSZ    (HH*WW)            /* 14400  */
#define IMG_SZ  1920.0f
#define KPOS    128
#define KNEG    60
#define NR      10                  /* ladder rungs */
#define CAP     4096                /* survivor capacity in shared */

// static pre-filter thresholds (float bit patterns; u >= T -> high tier)
#define TP_HI   0x3F400000u         /* 0.75      : keep ~1/4  of positives */
#define TN_HI   0x3F7C0000u         /* 0.984375  : keep ~1/64 of negatives */

// ---------------- static device scratch (no allocations) ----------------
__device__ uint2  g_pos[N_IMG * A_ANCH];   // low tier grows up, high tier grows down
__device__ uint2  g_neg[N_IMG * A_ANCH];
__device__ int    g_cnt[N_IMG * 4];        // [n][0]=pos_lo 1=pos_hi 2=neg_lo 3=neg_hi
__device__ float4 g_part[N_IMG][2];        // (bce, pred, l1, count)
__device__ int    g_ticket;                // zero-init; reset by last block

__constant__ float4 c_gt[N_IMG * M_GT];

struct Keys { unsigned kp0[N_IMG], kp1[N_IMG], kn0[N_IMG], kn1[N_IMG]; };

// ---------------- threefry2x32 (JAX-exact) ----------------
__host__ __device__ __forceinline__ unsigned rotl32(unsigned x, int d) {
    return (x << d) | (x >> (32 - d));
}
__host__ __device__ __forceinline__ void tf2x32(unsigned k0, unsigned k1,
                                                unsigned x0, unsigned x1,
                                                unsigned& o0, unsigned& o1) {
    unsigned ks2 = k0 ^ k1 ^ 0x1BD11BDAu;
    x0 += k0; x1 += k1;
#define TFR(r) { x0 += x1; x1 = rotl32(x1, r); x1 ^= x0; }
    TFR(13) TFR(15) TFR(26) TFR(6)   x0 += k1;  x1 += ks2 + 1u;
    TFR(17) TFR(29) TFR(16) TFR(24)  x0 += ks2; x1 += k0  + 2u;
    TFR(13) TFR(15) TFR(26) TFR(6)   x0 += k0;  x1 += k1  + 3u;
    TFR(17) TFR(29) TFR(16) TFR(24)  x0 += k1;  x1 += ks2 + 4u;
    TFR(13) TFR(15) TFR(26) TFR(6)   x0 += ks2; x1 += k0  + 5u;
#undef TFR
    o0 = x0; o1 = x1;
}

__device__ __forceinline__ unsigned ubits(unsigned k0, unsigned k1, int i) {
    unsigned o0, o1;
    tf2x32(k0, k1, 0u, (unsigned)i, o0, o1);
    unsigned b = o0 ^ o1;
    float u = __uint_as_float((b >> 9) | 0x3f800000u) - 1.0f;   // [0,1)
    return __float_as_uint(u);
}

// ---------------- geometry helpers ----------------
__device__ __forceinline__ void anchor_box(int k, int h, int w,
                                           float& ax1, float& ay1, float& ax2, float& ay2) {
    int r = k / 3, s = k % 3;
    float scale = (s == 0) ? 8.0f : ((s == 1) ? 16.0f : 32.0f);
    float sq2 = sqrtf(2.0f), sqh = sqrtf(0.5f);
    float srw = (r == 0) ? sq2 : ((r == 1) ? 1.0f : sqh);
    float srh = (r == 0) ? sqh : ((r == 1) ? 1.0f : sq2);
    float wsz = __fmul_rn(16.0f * scale, srw);
    float hsz = __fmul_rn(16.0f * scale, srh);
    float cx = __fmul_rn((float)w + 0.5f, 16.0f);
    float cy = __fmul_rn((float)h + 0.5f, 16.0f);
    float hw2 = __fmul_rn(wsz, 0.5f), hh2 = __fmul_rn(hsz, 0.5f);
    ax1 = __fsub_rn(cx, hw2); ay1 = __fsub_rn(cy, hh2);
    ax2 = __fadd_rn(cx, hw2); ay2 = __fadd_rn(cy, hh2);
}

__device__ __forceinline__ void region_box(const float* __restrict__ deltas,
                                           int n, int k, int h, int w,
                                           float ax1, float ay1, float ax2, float ay2,
                                           float& rx1, float& ry1, float& rx2, float& ry2) {
    int db = ((n * 4 * K_ANC + k * 4) * HH + h) * WW + w;
    rx1 = fminf(fmaxf(__fadd_rn(ax1, deltas[db          ]), 0.0f), IMG_SZ);
    ry1 = fminf(fmaxf(__fadd_rn(ay1, deltas[db +   HWSZ ]), 0.0f), IMG_SZ);
    rx2 = fminf(fmaxf(__fadd_rn(ax2, deltas[db + 2*HWSZ ]), 0.0f), IMG_SZ);
    ry2 = fminf(fmaxf(__fadd_rn(ay2, deltas[db + 3*HWSZ ]), 0.0f), IMG_SZ);
}

__device__ __forceinline__ int cls_index(int n, int a) {
    int k = a % K_ANC; int hw = a / K_ANC; int w = hw % WW; int h = hw / WW;
    return ((n * K_ANC + k) * HH + h) * WW + w;
}

__device__ __forceinline__ float softplusf(float x) {
    return fmaxf(x, 0.0f) + log1pf(expf(-fabsf(x)));
}
__device__ __forceinline__ float sl1(float d) {
    float ad = fabsf(d);
    return (ad < 0.1f) ? (0.5f * d * d / 0.1f) : (ad - 0.05f);
}

__device__ void pos_contrib(const float* __restrict__ cls, const float* __restrict__ deltas,
                            const float* __restrict__ gt, int n, int a, int m,
                            float& bce, float& pred, float& l1) {
    int k = a % K_ANC; int hw = a / K_ANC; int w = hw % WW; int h = hw / WW;
    float ax1, ay1, ax2, ay2;
    anchor_box(k, h, w, ax1, ay1, ax2, ay2);
    float rx1, ry1, rx2, ry2;
    region_box(deltas, n, k, h, w, ax1, ay1, ax2, ay2, rx1, ry1, rx2, ry2);
    float aw = __fsub_rn(ax2, ax1), ah = __fsub_rn(ay2, ay1);
    float acx = ax1 + 0.5f * aw, acy = ay1 + 0.5f * ah;
    float bw = fmaxf(__fsub_rn(rx2, rx1), 1e-6f), bh = fmaxf(__fsub_rn(ry2, ry1), 1e-6f);
    float bcx = rx1 + 0.5f * bw, bcy = ry1 + 0.5f * bh;
    float tp0 = (bcx - acx) / aw, tp1 = (bcy - acy) / ah;
    float tp2 = logf(bw / aw),    tp3 = logf(bh / ah);
    const float* g = gt + (n * M_GT + m) * 4;
    float gw = fmaxf(__fsub_rn(g[2], g[0]), 1e-6f), gh = fmaxf(__fsub_rn(g[3], g[1]), 1e-6f);
    float gcx = g[0] + 0.5f * gw, gcy = g[1] + 0.5f * gh;
    float tg0 = (gcx - acx) / aw, tg1 = (gcy - acy) / ah;
    float tg2 = logf(gw / aw),    tg3 = logf(gh / ah);
    l1 += sl1(tp0 - tg0) + sl1(tp1 - tg1) + sl1(tp2 - tg2) + sl1(tp3 - tg3);
    float x = cls[((n * K_ANC + k) * HH + h) * WW + w];
    bce += softplusf(-x); pred += x;
}

// ---------------- kernel 1: region + IoU match + tiered compaction ----------------
#define K1_THREADS 320
__global__ __launch_bounds__(K1_THREADS) void k_match(
        const float* __restrict__ deltas, Keys keys) {
    int n = blockIdx.y;
    __shared__ float  sag[M_GT];
    __shared__ int    scnt[4];
    __shared__ int    sbase[4];
    __shared__ int    wboff[K1_THREADS / 32][4];
    int tid = threadIdx.x;
    if (tid < M_GT) {
        float4 b = c_gt[n * M_GT + tid];
        sag[tid] = __fmul_rn(fmaxf(__fsub_rn(b.z, b.x), 0.0f),
                             fmaxf(__fsub_rn(b.w, b.y), 0.0f));
    }
    if (tid < 4) scnt[tid] = 0;
    __syncthreads();

    int t = blockIdx.x * K1_THREADS + tid;
    int k = t / HWSZ; int hw = t % HWSZ; int h = hw / WW; int w = hw % WW;
    int a = hw * K_ANC + k;

    float ax1, ay1, ax2, ay2;
    anchor_box(k, h, w, ax1, ay1, ax2, ay2);
    float rx1, ry1, rx2, ry2;
    region_box(deltas, n, k, h, w, ax1, ay1, ax2, ay2, rx1, ry1, rx2, ry2);
    float ab = __fmul_rn(fmaxf(__fsub_rn(rx2, rx1), 0.0f),
                         fmaxf(__fsub_rn(ry2, ry1), 0.0f));

    // warp-union bbox for GT culling (skipped pairs provably have inter == 0)
    float wx1 = rx1, wy1 = ry1, wx2 = rx2, wy2 = ry2;
#pragma unroll
    for (int o = 16; o > 0; o >>= 1) {
        wx1 = fminf(wx1, __shfl_xor_sync(0xffffffffu, wx1, o));
        wy1 = fminf(wy1, __shfl_xor_sync(0xffffffffu, wy1, o));
        wx2 = fmaxf(wx2, __shfl_xor_sync(0xffffffffu, wx2, o));
        wy2 = fmaxf(wy2, __shfl_xor_sync(0xffffffffu, wy2, o));
    }

    float best = 0.0f; int arg = 0;
    const float4* gbase = &c_gt[n * M_GT];
#pragma unroll 4
    for (int m = 0; m < M_GT; m++) {
        float4 g = gbase[m];                       // uniform -> const port
        if (wx2 > g.x && g.z > wx1 && wy2 > g.y && g.w > wy1) {
            float ix1 = fmaxf(rx1, g.x), iy1 = fmaxf(ry1, g.y);
            float ix2 = fminf(rx2, g.z), iy2 = fminf(ry2, g.w);
            float inter = __fmul_rn(fmaxf(__fsub_rn(ix2, ix1), 0.0f),
                                    fmaxf(__fsub_rn(iy2, iy1), 0.0f));
            float den = __fadd_rn(__fsub_rn(__fadd_rn(ab, sag[m]), inter), 1e-6f);
            if (inter > __fmul_rn(__fmul_rn(best, den), 0.9999995f) && inter > 0.0f) {
                float iou = __fdiv_rn(inter, den);
                if (iou > best) { best = iou; arg = m; }
            }
        }
    }
    int match = (best >= 0.4f) ? arg : ((best < 0.1f) ? -1 : -2);
    unsigned ub = 0u;
    if (match >= 0)       ub = ubits(keys.kp0[n], keys.kp1[n], a);
    else if (match == -1) ub = ubits(keys.kn0[n], keys.kn1[n], a);
    bool isp = (match >= 0) && (ub != 0u);
    bool isn = (match == -1) && (ub != 0u);
    bool hip = isp && (ub >= TP_HI);
    bool hin = isn && (ub >= TN_HI);

    int wid = tid >> 5, lane = tid & 31;
    unsigned m0 = __ballot_sync(0xffffffffu, isp && !hip);   // pos low
    unsigned m1 = __ballot_sync(0xffffffffu, hip);           // pos high
    unsigned m2 = __ballot_sync(0xffffffffu, isn && !hin);   // neg low
    unsigned m3 = __ballot_sync(0xffffffffu, hin);           // neg high
    if (lane == 0) {
        wboff[wid][0] = atomicAdd(&scnt[0], __popc(m0));
        wboff[wid][1] = atomicAdd(&scnt[1], __popc(m1));
        wboff[wid][2] = atomicAdd(&scnt[2], __popc(m2));
        wboff[wid][3] = atomicAdd(&scnt[3], __popc(m3));
    }
    __syncthreads();
    if (tid < 4) sbase[tid] = atomicAdd(&g_cnt[n * 4 + tid], scnt[tid]);
    __syncthreads();
    unsigned lm = (1u << lane) - 1u;
    if (isp) {
        uint2 e = make_uint2(ub, (unsigned)a | ((unsigned)arg << 17));
        if (hip) {
            int p = sbase[1] + wboff[wid][1] + __popc(m1 & lm);
            g_pos[n * A_ANCH + (A_ANCH - 1 - p)] = e;
        } else {
            int p = sbase[0] + wboff[wid][0] + __popc(m0 & lm);
            g_pos[n * A_ANCH + p] = e;
        }
    }
    if (isn) {
        uint2 e = make_uint2(ub, (unsigned)a);
        if (hin) {
            int p = sbase[3] + wboff[wid][3] + __popc(m3 & lm);
            g_neg[n * A_ANCH + (A_ANCH - 1 - p)] = e;
        } else {
            int p = sbase[2] + wboff[wid][2] + __popc(m2 & lm);
            g_neg[n * A_ANCH + p] = e;
        }
    }
}

// ---------------- kernel 2: exact top-K + loss reduce + finalize ----------------
__device__ __forceinline__ bool pair_less(uint2 A, uint2 B) {
    if (A.x != B.x) return A.x < B.x;
    return (A.y & 0x1FFFFu) > (B.y & 0x1FFFFu);
}

__global__ __launch_bounds__(1024) void k_select(
        const float* __restrict__ cls, const float* __restrict__ deltas,
        const float* __restrict__ gt, float* out, int out_size) {
    int bx = blockIdx.x;
    int n = bx >> 1, cat = bx & 1;                 // 0 = pos, 1 = neg
    int tid = threadIdx.x;
    int wid = tid >> 5, lane = tid & 31;
    const uint2* base = (cat ? g_neg : g_pos) + n * A_ANCH;

    // RACE FIX: single-owner read+reset, broadcast via shared, then sync.
    __shared__ int sClo, sChi;
    if (tid == 0) {
        sClo = g_cnt[n * 4 + cat * 2 + 0];
        sChi = g_cnt[n * 4 + cat * 2 + 1];
        g_cnt[n * 4 + cat * 2 + 0] = 0;            // safe: same-thread program order
        g_cnt[n * 4 + cat * 2 + 1] = 0;
    }
    __syncthreads();
    int Clo = sClo, Chi = sChi;
    int Ctot = Clo + Chi;
    int K = cat ? KNEG : KPOS;
    int need = min(K, Ctot);

    // segment view: high tier always; low tier only when high can't cover top-K
    const uint2* segA = base + (A_ANCH - Chi);
    int LA = Chi;
    int LB = (Chi >= need) ? 0 : Clo;
    int L = LA + LB;
    auto LD = [&](int i) -> uint2 { return (i < LA) ? segA[i] : base[i - LA]; };

    __shared__ unsigned sth[NR];
    __shared__ int stot[NR];
    __shared__ uint2 ss[CAP];
    __shared__ int   swarp[32];
    __shared__ float fwarp[32];
    __shared__ unsigned sT;
    __shared__ int sS, sLo, sHi, sFlag, scap;

    if (tid == 0) {
        float invC = 1.0f / (float)max(Ctot, 1);   // quantiles w.r.t. full population
        for (int j = 0; j < NR - 1; j++) {
            float u = 1.0f - (float)((2 << j) * K) * invC;
            sth[j] = (u <= 0.0f) ? 1u : __float_as_uint(u);
        }
        sth[NR - 1] = 1u;
        scap = 0;
    }
    __syncthreads();

    // ---- single scan: ladder counts + opportunistic capture at rung 0 ----
    unsigned T0 = sth[0];
    int cnt[NR];
#pragma unroll
    for (int j = 0; j < NR; j++) cnt[j] = 0;
    for (int i = tid; i < L; i += 1024) {
        uint2 e = LD(i);
        unsigned v = e.x;
#pragma unroll
        for (int j = 0; j < NR; j++) cnt[j] += (v >= sth[j]);
        if (v >= T0) {
            int p = atomicAdd(&scap, 1);
            if (p < CAP) ss[p] = e;
        }
    }
    for (int j = 0; j < NR; j++) {
        int r = cnt[j];
#pragma unroll
        for (int o = 16; o > 0; o >>= 1) r += __shfl_down_sync(0xffffffffu, r, o);
        if (lane == 0) swarp[wid] = r;
        __syncthreads();
        if (tid == 0) {
            int s = 0;
            for (int q = 0; q < 32; q++) s += swarp[q];
            stot[j] = s;
        }
        __syncthreads();
    }
    bool usable0 = (stot[0] >= need) && (stot[0] <= CAP);
    int S;
    if (usable0) {
        S = stot[0];
    } else {
        if (tid == 0) {
            int rung = NR - 1;
            for (int j = 0; j < NR; j++) if (stot[j] >= need) { rung = j; break; }
            sT = sth[rung]; sS = stot[rung];
            sLo = rung;
            sFlag = (stot[rung] > CAP) ? 1 : 0;
        }
        __syncthreads();
        while (sFlag) {
            __syncthreads();
            if (tid == 0) {
                int rung = sLo;
                unsigned lo = sth[rung];
                unsigned hi = (rung > 0) ? sth[rung - 1] : 0xFFFFFFFFu;
                sLo = (int)lo; sHi = (int)hi;
            }
            __syncthreads();
            for (int iter = 0; iter < 34; iter++) {
                unsigned lo = (unsigned)sLo, hi = (unsigned)sHi;
                if (hi - lo <= 1u) break;
                unsigned mid = lo + ((hi - lo) >> 1);
                int c = 0;
                for (int i = tid; i < L; i += 1024) c += (LD(i).x >= mid);
#pragma unroll
                for (int o = 16; o > 0; o >>= 1) c += __shfl_down_sync(0xffffffffu, c, o);
                if (lane == 0) swarp[wid] = c;
                __syncthreads();
                if (tid == 0) {
                    int s = 0;
                    for (int q = 0; q < 32; q++) s += swarp[q];
                    if (s >= need) { sLo = (int)mid; sT = mid; sS = s; }
                    else           { sHi = (int)mid; }
                }
                __syncthreads();
            }
            if (tid == 0) sFlag = 0;
            __syncthreads();
        }
        if (tid == 0) scap = 0;
        __syncthreads();
        unsigned T = sT;
        for (int i = tid; i < L; i += 1024) {
            uint2 e = LD(i);
            if (e.x >= T) {
                int p = atomicAdd(&scap, 1);
                if (p < CAP) ss[p] = e;
            }
        }
        __syncthreads();
        S = min(sS, CAP);
    }
    __syncthreads();

    // ---- pad + bitonic sort ascending (value asc, index desc) ----
    int Npow = 1; while (Npow < S) Npow <<= 1;
    for (int i = S + tid; i < Npow; i += 1024) ss[i] = make_uint2(0u, 0x1FFFFu);
    __syncthreads();
    for (unsigned sz = 2; sz <= (unsigned)Npow; sz <<= 1) {
        for (unsigned st = sz >> 1; st > 0; st >>= 1) {
            for (int i = tid; i < Npow; i += 1024) {
                int j = i ^ (int)st;
                if (j > i) {
                    uint2 A = ss[i], B = ss[j];
                    bool up = ((i & sz) == 0);
                    bool sw = up ? pair_less(B, A) : pair_less(A, B);
                    if (sw) { ss[i] = B; ss[j] = A; }
                }
            }
            __syncthreads();
        }
    }

    // ---- accumulate top `need` ----
    float b = 0.0f, p = 0.0f, l = 0.0f;
    if (tid < need) {
        uint2 e = ss[Npow - 1 - tid];
        int a = (int)(e.y & 0x1FFFFu);
        if (cat) {
            float x = cls[cls_index(n, a)];
            b = softplusf(x); p = x;
        } else {
            int m = (int)(e.y >> 17);
            pos_contrib(cls, deltas, gt, n, a, m, b, p, l);
        }
    }
    float vals[3] = {b, p, l};
    float out3[3];
    for (int q = 0; q < 3; q++) {
        float v = vals[q];
#pragma unroll
        for (int o = 16; o > 0; o >>= 1) v += __shfl_down_sync(0xffffffffu, v, o);
        if (lane == 0) fwarp[wid] = v;
        __syncthreads();
        if (tid == 0) {
            float s = 0.0f;
            for (int w2 = 0; w2 < 32; w2++) s += fwarp[w2];
            out3[q] = s;
        }
        __syncthreads();
    }

    if (tid == 0) {
        g_part[n][cat] = make_float4(out3[0], out3[1], out3[2], (float)need);
        __threadfence();
        int ticket = atomicAdd(&g_ticket, 1);
        if (ticket == N_IMG * 2 - 1) {
            __threadfence();
            float cl = 0.f, bl = 0.f, fg = 0.f, bg = 0.f, pm = 0.f;
            for (int q = 0; q < N_IMG; q++) {
                volatile float* Pp = (volatile float*)&g_part[q][0];
                volatile float* Gg = (volatile float*)&g_part[q][1];
                float Pb = Pp[0], Pd = Pp[1], Pl = Pp[2], np = Pp[3];
                float Gb = Gg[0], Gd = Gg[1], nn = Gg[3];
                float denom = fmaxf(np + nn, 1.0f);
                cl += (Pb + Gb) / denom;
                bl += Pl / (fmaxf(np, 1.0f) * (float)N_IMG);
                fg += np; bg += nn;
                if (q == N_IMG - 1) pm = (Pd + Gd) / denom;
            }
            out[0] = cl; out[1] = bl; out[2] = bg; out[3] = fg; out[4] = pm;
            for (int i = 5; i < out_size; i++) out[i] = 0.0f;
            g_ticket = 0;
        }
    }
}

// ---------------- host launcher ----------------
extern "C" void kernel_launch(void* const* d_in, const int* in_sizes, int n_in,
                              void* d_out, int out_size) {
    (void)in_sizes; (void)n_in;
    const float* cls    = (const float*)d_in[0];
    const float* deltas = (const float*)d_in[1];
    const float* gt     = (const float*)d_in[2];
    float* out = (float*)d_out;

    Keys keys;
    for (int n = 0; n < N_IMG; n++) {
        unsigned K0, K1;
        tf2x32(0u, 42u, 0u, (unsigned)n, K0, K1);
        unsigned p0, p1, q0, q1;
        tf2x32(K0, K1, 0u, 0u, p0, p1);
        tf2x32(K0, K1, 0u, 1u, q0, q1);
        keys.kp0[n] = p0; keys.kp1[n] = p1;
        keys.kn0[n] = q0; keys.kn1[n] = q1;
    }

    cudaMemcpyToSymbolAsync(c_gt, gt, N_IMG * M_GT * sizeof(float4), 0,
                            cudaMemcpyDeviceToDevice, 0);

    dim3 g1(A_ANCH / K1_THREADS, N_IMG);                   // 405 x 8
    k_match<<<g1, K1_THREADS>>>(deltas, keys);
    k_select<<<N_IMG * 2, 1024>>>(cls, deltas, gt, out, out_size);
}

// round 6
// speedup vs baseline: 5.8230x; 1.2703x over previous
#include <cuda_runtime.h>
#include <cstdint>

// ---------------- problem constants (fixed shapes) ----------------
#define N_IMG   8
#define K_ANC   9
#define HH      120
#define WW      120
#define M_GT    64
#define A_ANCH  (HH*WW*K_ANC)      /* 129600 */
#define HWSZ    (HH*WW)            /* 14400  */
#define IMG_SZ  1920.0f
#define KPOS    128
#define KNEG    60
#define CAP     4096                /* survivor capacity in shared */

// static pre-filter thresholds (float bit patterns; u >= T -> high tier)
#define TP_HI   0x3F400000u         /* 0.75      : keep ~1/4  of positives */
#define TN_HI   0x3F7C0000u         /* 0.984375  : keep ~1/64 of negatives */

// ---------------- static device scratch (no allocations) ----------------
__device__ uint2  g_pos[N_IMG * A_ANCH];   // low tier grows up, high tier grows down
__device__ uint2  g_neg[N_IMG * A_ANCH];
__device__ int    g_cnt[N_IMG * 4];        // [n][0]=pos_lo 1=pos_hi 2=neg_lo 3=neg_hi
__device__ float4 g_part[N_IMG][2];        // (bce, pred, l1, count)
__device__ int    g_ticket;                // zero-init; reset by last block

__constant__ float4 c_gt[N_IMG * M_GT];

struct Keys { unsigned kp0[N_IMG], kp1[N_IMG], kn0[N_IMG], kn1[N_IMG]; };

// ---------------- threefry2x32 (JAX-exact) ----------------
__host__ __device__ __forceinline__ unsigned rotl32(unsigned x, int d) {
    return (x << d) | (x >> (32 - d));
}
__host__ __device__ __forceinline__ void tf2x32(unsigned k0, unsigned k1,
                                                unsigned x0, unsigned x1,
                                                unsigned& o0, unsigned& o1) {
    unsigned ks2 = k0 ^ k1 ^ 0x1BD11BDAu;
    x0 += k0; x1 += k1;
#define TFR(r) { x0 += x1; x1 = rotl32(x1, r); x1 ^= x0; }
    TFR(13) TFR(15) TFR(26) TFR(6)   x0 += k1;  x1 += ks2 + 1u;
    TFR(17) TFR(29) TFR(16) TFR(24)  x0 += ks2; x1 += k0  + 2u;
    TFR(13) TFR(15) TFR(26) TFR(6)   x0 += k0;  x1 += k1  + 3u;
    TFR(17) TFR(29) TFR(16) TFR(24)  x0 += k1;  x1 += ks2 + 4u;
    TFR(13) TFR(15) TFR(26) TFR(6)   x0 += ks2; x1 += k0  + 5u;
#undef TFR
    o0 = x0; o1 = x1;
}

__device__ __forceinline__ unsigned ubits(unsigned k0, unsigned k1, int i) {
    unsigned o0, o1;
    tf2x32(k0, k1, 0u, (unsigned)i, o0, o1);
    unsigned b = o0 ^ o1;
    float u = __uint_as_float((b >> 9) | 0x3f800000u) - 1.0f;   // [0,1)
    return __float_as_uint(u);
}

// ---------------- geometry helpers ----------------
__device__ __forceinline__ void anchor_box(int k, int h, int w,
                                           float& ax1, float& ay1, float& ax2, float& ay2) {
    int r = k / 3, s = k % 3;
    float scale = (s == 0) ? 8.0f : ((s == 1) ? 16.0f : 32.0f);
    float sq2 = sqrtf(2.0f), sqh = sqrtf(0.5f);
    float srw = (r == 0) ? sq2 : ((r == 1) ? 1.0f : sqh);
    float srh = (r == 0) ? sqh : ((r == 1) ? 1.0f : sq2);
    float wsz = __fmul_rn(16.0f * scale, srw);
    float hsz = __fmul_rn(16.0f * scale, srh);
    float cx = __fmul_rn((float)w + 0.5f, 16.0f);
    float cy = __fmul_rn((float)h + 0.5f, 16.0f);
    float hw2 = __fmul_rn(wsz, 0.5f), hh2 = __fmul_rn(hsz, 0.5f);
    ax1 = __fsub_rn(cx, hw2); ay1 = __fsub_rn(cy, hh2);
    ax2 = __fadd_rn(cx, hw2); ay2 = __fadd_rn(cy, hh2);
}

__device__ __forceinline__ void region_box(const float* __restrict__ deltas,
                                           int n, int k, int h, int w,
                                           float ax1, float ay1, float ax2, float ay2,
                                           float& rx1, float& ry1, float& rx2, float& ry2) {
    int db = ((n * 4 * K_ANC + k * 4) * HH + h) * WW + w;
    rx1 = fminf(fmaxf(__fadd_rn(ax1, deltas[db          ]), 0.0f), IMG_SZ);
    ry1 = fminf(fmaxf(__fadd_rn(ay1, deltas[db +   HWSZ ]), 0.0f), IMG_SZ);
    rx2 = fminf(fmaxf(__fadd_rn(ax2, deltas[db + 2*HWSZ ]), 0.0f), IMG_SZ);
    ry2 = fminf(fmaxf(__fadd_rn(ay2, deltas[db + 3*HWSZ ]), 0.0f), IMG_SZ);
}

__device__ __forceinline__ int cls_index(int n, int a) {
    int k = a % K_ANC; int hw = a / K_ANC; int w = hw % WW; int h = hw / WW;
    return ((n * K_ANC + k) * HH + h) * WW + w;
}

__device__ __forceinline__ float softplusf(float x) {
    return fmaxf(x, 0.0f) + log1pf(expf(-fabsf(x)));
}
__device__ __forceinline__ float sl1(float d) {
    float ad = fabsf(d);
    return (ad < 0.1f) ? (0.5f * d * d / 0.1f) : (ad - 0.05f);
}

__device__ void pos_contrib(const float* __restrict__ cls, const float* __restrict__ deltas,
                            const float* __restrict__ gt, int n, int a, int m,
                            float& bce, float& pred, float& l1) {
    int k = a % K_ANC; int hw = a / K_ANC; int w = hw % WW; int h = hw / WW;
    float ax1, ay1, ax2, ay2;
    anchor_box(k, h, w, ax1, ay1, ax2, ay2);
    float rx1, ry1, rx2, ry2;
    region_box(deltas, n, k, h, w, ax1, ay1, ax2, ay2, rx1, ry1, rx2, ry2);
    float aw = __fsub_rn(ax2, ax1), ah = __fsub_rn(ay2, ay1);
    float acx = ax1 + 0.5f * aw, acy = ay1 + 0.5f * ah;
    float bw = fmaxf(__fsub_rn(rx2, rx1), 1e-6f), bh = fmaxf(__fsub_rn(ry2, ry1), 1e-6f);
    float bcx = rx1 + 0.5f * bw, bcy = ry1 + 0.5f * bh;
    float tp0 = (bcx - acx) / aw, tp1 = (bcy - acy) / ah;
    float tp2 = logf(bw / aw),    tp3 = logf(bh / ah);
    const float* g = gt + (n * M_GT + m) * 4;
    float gw = fmaxf(__fsub_rn(g[2], g[0]), 1e-6f), gh = fmaxf(__fsub_rn(g[3], g[1]), 1e-6f);
    float gcx = g[0] + 0.5f * gw, gcy = g[1] + 0.5f * gh;
    float tg0 = (gcx - acx) / aw, tg1 = (gcy - acy) / ah;
    float tg2 = logf(gw / aw),    tg3 = logf(gh / ah);
    l1 += sl1(tp0 - tg0) + sl1(tp1 - tg1) + sl1(tp2 - tg2) + sl1(tp3 - tg3);
    float x = cls[((n * K_ANC + k) * HH + h) * WW + w];
    bce += softplusf(-x); pred += x;
}

// ---------------- kernel 1: region + IoU match + tiered compaction ----------------
#define K1_THREADS 320
__global__ __launch_bounds__(K1_THREADS) void k_match(
        const float* __restrict__ deltas, Keys keys) {
    int n = blockIdx.y;
    __shared__ float4 sg[M_GT];
    __shared__ int    scnt[4];
    __shared__ int    sbase[4];
    __shared__ int    wboff[K1_THREADS / 32][4];
    int tid = threadIdx.x;
    if (tid < M_GT) sg[tid] = c_gt[n * M_GT + tid];
    if (tid < 4) scnt[tid] = 0;
    __syncthreads();

    int t = blockIdx.x * K1_THREADS + tid;
    int k = t / HWSZ; int hw = t % HWSZ; int h = hw / WW; int w = hw % WW;
    int a = hw * K_ANC + k;

    float ax1, ay1, ax2, ay2;
    anchor_box(k, h, w, ax1, ay1, ax2, ay2);
    float rx1, ry1, rx2, ry2;
    region_box(deltas, n, k, h, w, ax1, ay1, ax2, ay2, rx1, ry1, rx2, ry2);
    float ab = __fmul_rn(fmaxf(__fsub_rn(rx2, rx1), 0.0f),
                         fmaxf(__fsub_rn(ry2, ry1), 0.0f));

    // warp-union bbox (skipped GTs provably have inter == 0 for every lane)
    float wx1 = rx1, wy1 = ry1, wx2 = rx2, wy2 = ry2;
#pragma unroll
    for (int o = 16; o > 0; o >>= 1) {
        wx1 = fminf(wx1, __shfl_xor_sync(0xffffffffu, wx1, o));
        wy1 = fminf(wy1, __shfl_xor_sync(0xffffffffu, wy1, o));
        wx2 = fmaxf(wx2, __shfl_xor_sync(0xffffffffu, wx2, o));
        wy2 = fmaxf(wy2, __shfl_xor_sync(0xffffffffu, wy2, o));
    }

    // ballot-compacted survivor masks: lane tests GT[lane] and GT[lane+32]
    int lane = tid & 31;
    float4 gA = sg[lane];
    float4 gB = sg[lane + 32];
    bool oA = (wx2 > gA.x) && (gA.z > wx1) && (wy2 > gA.y) && (gA.w > wy1);
    bool oB = (wx2 > gB.x) && (gB.z > wx1) && (wy2 > gB.y) && (gB.w > wy1);
    unsigned mA = __ballot_sync(0xffffffffu, oA);
    unsigned mB = __ballot_sync(0xffffffffu, oB);

    float best = 0.0f; int arg = 0;
    const float4* gbase = &c_gt[n * M_GT];
    unsigned mm = mA; int mofs = 0;
#pragma unroll 1
    for (int half = 0; half < 2; half++) {
        while (mm) {
            int m = (__ffs(mm) - 1) + mofs;        // increasing m: first-tie preserved
            mm &= mm - 1;
            float4 g = gbase[m];                   // uniform -> const port
            float ag = __fmul_rn(fmaxf(__fsub_rn(g.z, g.x), 0.0f),
                                 fmaxf(__fsub_rn(g.w, g.y), 0.0f));
            float ix1 = fmaxf(rx1, g.x), iy1 = fmaxf(ry1, g.y);
            float ix2 = fminf(rx2, g.z), iy2 = fminf(ry2, g.w);
            float inter = __fmul_rn(fmaxf(__fsub_rn(ix2, ix1), 0.0f),
                                    fmaxf(__fsub_rn(iy2, iy1), 0.0f));
            float den = __fadd_rn(__fsub_rn(__fadd_rn(ab, ag), inter), 1e-6f);
            if (inter > __fmul_rn(__fmul_rn(best, den), 0.9999995f) && inter > 0.0f) {
                float iou = __fdiv_rn(inter, den);
                if (iou > best) { best = iou; arg = m; }
            }
        }
        mm = mB; mofs = 32;
    }

    int match = (best >= 0.4f) ? arg : ((best < 0.1f) ? -1 : -2);
    unsigned ub = 0u;
    if (match >= 0)       ub = ubits(keys.kp0[n], keys.kp1[n], a);
    else if (match == -1) ub = ubits(keys.kn0[n], keys.kn1[n], a);
    bool isp = (match >= 0) && (ub != 0u);
    bool isn = (match == -1) && (ub != 0u);
    bool hip = isp && (ub >= TP_HI);
    bool hin = isn && (ub >= TN_HI);

    int wid = tid >> 5;
    unsigned m0 = __ballot_sync(0xffffffffu, isp && !hip);
    unsigned m1 = __ballot_sync(0xffffffffu, hip);
    unsigned m2 = __ballot_sync(0xffffffffu, isn && !hin);
    unsigned m3 = __ballot_sync(0xffffffffu, hin);
    if (lane == 0) {
        wboff[wid][0] = atomicAdd(&scnt[0], __popc(m0));
        wboff[wid][1] = atomicAdd(&scnt[1], __popc(m1));
        wboff[wid][2] = atomicAdd(&scnt[2], __popc(m2));
        wboff[wid][3] = atomicAdd(&scnt[3], __popc(m3));
    }
    __syncthreads();
    if (tid < 4) sbase[tid] = atomicAdd(&g_cnt[n * 4 + tid], scnt[tid]);
    __syncthreads();
    unsigned lm = (1u << lane) - 1u;
    if (isp) {
        uint2 e = make_uint2(ub, (unsigned)a | ((unsigned)arg << 17));
        if (hip) {
            int p = sbase[1] + wboff[wid][1] + __popc(m1 & lm);
            g_pos[n * A_ANCH + (A_ANCH - 1 - p)] = e;
        } else {
            int p = sbase[0] + wboff[wid][0] + __popc(m0 & lm);
            g_pos[n * A_ANCH + p] = e;
        }
    }
    if (isn) {
        uint2 e = make_uint2(ub, (unsigned)a);
        if (hin) {
            int p = sbase[3] + wboff[wid][3] + __popc(m3 & lm);
            g_neg[n * A_ANCH + (A_ANCH - 1 - p)] = e;
        } else {
            int p = sbase[2] + wboff[wid][2] + __popc(m2 & lm);
            g_neg[n * A_ANCH + p] = e;
        }
    }
}

// ---------------- kernel 2: exact top-K + loss reduce + finalize ----------------
#define K2_THREADS 256
#define K2_WARPS   (K2_THREADS / 32)

__device__ __forceinline__ bool pair_less(uint2 A, uint2 B) {
    if (A.x != B.x) return A.x < B.x;
    return (A.y & 0x1FFFFu) > (B.y & 0x1FFFFu);
}

__global__ __launch_bounds__(K2_THREADS) void k_select(
        const float* __restrict__ cls, const float* __restrict__ deltas,
        const float* __restrict__ gt, float* out, int out_size) {
    int bx = blockIdx.x;
    int n = bx >> 1, cat = bx & 1;                 // 0 = pos, 1 = neg
    int tid = threadIdx.x;
    int wid = tid >> 5, lane = tid & 31;
    const uint2* base = (cat ? g_neg : g_pos) + n * A_ANCH;

    __shared__ int sClo, sChi;
    if (tid == 0) {
        sClo = g_cnt[n * 4 + cat * 2 + 0];
        sChi = g_cnt[n * 4 + cat * 2 + 1];
        g_cnt[n * 4 + cat * 2 + 0] = 0;            // single-owner read+reset
        g_cnt[n * 4 + cat * 2 + 1] = 0;
    }
    __syncthreads();
    int Clo = sClo, Chi = sChi;
    int Ctot = Clo + Chi;
    int K = cat ? KNEG : KPOS;
    int need = min(K, Ctot);

    // segment view: high tier always; low tier only when high can't cover top-K
    const uint2* segA = base + (A_ANCH - Chi);
    int LA = Chi;
    int LB = (Chi >= need) ? 0 : Clo;
    int L = LA + LB;
    auto LD = [&](int i) -> uint2 { return (i < LA) ? segA[i] : base[i - LA]; };

    __shared__ unsigned sth[2];
    __shared__ int stot[3];
    __shared__ uint2 ss[CAP];
    __shared__ int   swarp[K2_WARPS][4];
    __shared__ float fwarp[K2_WARPS][3];
    __shared__ unsigned sT;
    __shared__ int sS, sLo, sHi, sFlag, scap;

    if (tid == 0) {
        float invC = 1.0f / (float)max(Ctot, 1);   // quantiles w.r.t. full population
        float u0 = 1.0f - (float)(2 * K) * invC;
        float u1 = 1.0f - (float)(8 * K) * invC;
        sth[0] = (u0 <= 0.0f) ? 1u : __float_as_uint(u0);
        sth[1] = (u1 <= 0.0f) ? 1u : __float_as_uint(u1);
        scap = 0;
    }
    __syncthreads();

    // ---- single scan: 3 counts + opportunistic capture at rung 0 ----
    unsigned T0 = sth[0], T1 = sth[1];
    int c0 = 0, c1 = 0, c2 = 0;
    for (int i = tid; i < L; i += K2_THREADS) {
        uint2 e = LD(i);
        unsigned v = e.x;
        c0 += (v >= T0); c1 += (v >= T1); c2++;
        if (v >= T0) {
            int p = atomicAdd(&scap, 1);
            if (p < CAP) ss[p] = e;
        }
    }
#pragma unroll
    for (int o = 16; o > 0; o >>= 1) {
        c0 += __shfl_down_sync(0xffffffffu, c0, o);
        c1 += __shfl_down_sync(0xffffffffu, c1, o);
        c2 += __shfl_down_sync(0xffffffffu, c2, o);
    }
    if (lane == 0) { swarp[wid][0] = c0; swarp[wid][1] = c1; swarp[wid][2] = c2; }
    __syncthreads();
    if (tid < 3) {
        int s = 0;
        for (int q = 0; q < K2_WARPS; q++) s += swarp[q][tid];
        stot[tid] = s;
    }
    __syncthreads();

    int S;
    if (stot[0] >= need && stot[0] <= CAP) {
        S = stot[0];                               // common path: captured set is superset
    } else if (stot[1] >= need && stot[1] <= CAP) {
        if (tid == 0) scap = 0;
        __syncthreads();
        for (int i = tid; i < L; i += K2_THREADS) {
            uint2 e = LD(i);
            if (e.x >= T1) { int p = atomicAdd(&scap, 1); if (p < CAP) ss[p] = e; }
        }
        __syncthreads();
        S = stot[1];
    } else if (stot[2] <= CAP) {
        if (tid == 0) scap = 0;
        __syncthreads();
        for (int i = tid; i < L; i += K2_THREADS) {
            uint2 e = LD(i);
            int p = atomicAdd(&scap, 1); if (p < CAP) ss[p] = e;
        }
        __syncthreads();
        S = stot[2];
    } else {
        // exactness backstop: binary search tightest threshold with count in [need, CAP]
        if (tid == 0) {
            if (stot[1] >= need) { sLo = (int)T1; sHi = (int)T0; sT = T1; sS = stot[1]; }
            else                 { sLo = (int)1u; sHi = (int)T1; sT = 1u; sS = stot[2]; }
            sFlag = 1;
        }
        __syncthreads();
        for (int iter = 0; iter < 34 && sFlag; iter++) {
            unsigned lo = (unsigned)sLo, hi = (unsigned)sHi;
            if (hi - lo <= 1u) break;
            unsigned mid = lo + ((hi - lo) >> 1);
            int c = 0;
            for (int i = tid; i < L; i += K2_THREADS) c += (LD(i).x >= mid);
#pragma unroll
            for (int o = 16; o > 0; o >>= 1) c += __shfl_down_sync(0xffffffffu, c, o);
            if (lane == 0) swarp[wid][3] = c;
            __syncthreads();
            if (tid == 0) {
                int s = 0;
                for (int q = 0; q < K2_WARPS; q++) s += swarp[q][3];
                if (s >= need) { sLo = (int)mid; sT = mid; sS = s; }
                else           { sHi = (int)mid; }
                if (sS <= CAP) sFlag = 0;
            }
            __syncthreads();
        }
        if (tid == 0) scap = 0;
        __syncthreads();
        unsigned T = sT;
        for (int i = tid; i < L; i += K2_THREADS) {
            uint2 e = LD(i);
            if (e.x >= T) { int p = atomicAdd(&scap, 1); if (p < CAP) ss[p] = e; }
        }
        __syncthreads();
        S = min(sS, CAP);
    }
    __syncthreads();

    // ---- pad + bitonic sort ascending (value asc, index desc) ----
    int Npow = 1; while (Npow < S) Npow <<= 1;
    for (int i = S + tid; i < Npow; i += K2_THREADS) ss[i] = make_uint2(0u, 0x1FFFFu);
    __syncthreads();
    for (unsigned sz = 2; sz <= (unsigned)Npow; sz <<= 1) {
        for (unsigned st = sz >> 1; st > 0; st >>= 1) {
            for (int i = tid; i < Npow; i += K2_THREADS) {
                int j = i ^ (int)st;
                if (j > i) {
                    uint2 A = ss[i], B = ss[j];
                    bool up = ((i & sz) == 0);
                    bool sw = up ? pair_less(B, A) : pair_less(A, B);
                    if (sw) { ss[i] = B; ss[j] = A; }
                }
            }
            __syncthreads();
        }
    }

    // ---- accumulate top `need` (need <= 128 <= K2_THREADS) ----
    float b = 0.0f, p = 0.0f, l = 0.0f;
    if (tid < need) {
        uint2 e = ss[Npow - 1 - tid];
        int a = (int)(e.y & 0x1FFFFu);
        if (cat) {
            float x = cls[cls_index(n, a)];
            b = softplusf(x); p = x;
        } else {
            int m = (int)(e.y >> 17);
            pos_contrib(cls, deltas, gt, n, a, m, b, p, l);
        }
    }
#pragma unroll
    for (int o = 16; o > 0; o >>= 1) {
        b += __shfl_down_sync(0xffffffffu, b, o);
        p += __shfl_down_sync(0xffffffffu, p, o);
        l += __shfl_down_sync(0xffffffffu, l, o);
    }
    if (lane == 0) { fwarp[wid][0] = b; fwarp[wid][1] = p; fwarp[wid][2] = l; }
    __syncthreads();

    if (tid == 0) {
        float sb = 0.f, sp = 0.f, sl_ = 0.f;
        for (int q = 0; q < K2_WARPS; q++) {
            sb += fwarp[q][0]; sp += fwarp[q][1]; sl_ += fwarp[q][2];
        }
        g_part[n][cat] = make_float4(sb, sp, sl_, (float)need);
        __threadfence();
        int ticket = atomicAdd(&g_ticket, 1);
        if (ticket == N_IMG * 2 - 1) {
            __threadfence();
            float cl = 0.f, bl = 0.f, fg = 0.f, bg = 0.f, pm = 0.f;
            for (int q = 0; q < N_IMG; q++) {
                volatile float* Pp = (volatile float*)&g_part[q][0];
                volatile float* Gg = (volatile float*)&g_part[q][1];
                float Pb = Pp[0], Pd = Pp[1], Pl = Pp[2], np = Pp[3];
                float Gb = Gg[0], Gd = Gg[1], nn = Gg[3];
                float denom = fmaxf(np + nn, 1.0f);
                cl += (Pb + Gb) / denom;
                bl += Pl / (fmaxf(np, 1.0f) * (float)N_IMG);
                fg += np; bg += nn;
                if (q == N_IMG - 1) pm = (Pd + Gd) / denom;
            }
            out[0] = cl; out[1] = bl; out[2] = bg; out[3] = fg; out[4] = pm;
            for (int i = 5; i < out_size; i++) out[i] = 0.0f;
            g_ticket = 0;
        }
    }
}

// ---------------- host launcher ----------------
extern "C" void kernel_launch(void* const* d_in, const int* in_sizes, int n_in,
                              void* d_out, int out_size) {
    (void)in_sizes; (void)n_in;
    const float* cls    = (const float*)d_in[0];
    const float* deltas = (const float*)d_in[1];
    const float* gt     = (const float*)d_in[2];
    float* out = (float*)d_out;

    Keys keys;
    for (int n = 0; n < N_IMG; n++) {
        unsigned K0, K1;
        tf2x32(0u, 42u, 0u, (unsigned)n, K0, K1);
        unsigned p0, p1, q0, q1;
        tf2x32(K0, K1, 0u, 0u, p0, p1);
        tf2x32(K0, K1, 0u, 1u, q0, q1);
        keys.kp0[n] = p0; keys.kp1[n] = p1;
        keys.kn0[n] = q0; keys.kn1[n] = q1;
    }

    cudaMemcpyToSymbolAsync(c_gt, gt, N_IMG * M_GT * sizeof(float4), 0,
                            cudaMemcpyDeviceToDevice, 0);

    dim3 g1(A_ANCH / K1_THREADS, N_IMG);                   // 405 x 8
    k_match<<<g1, K1_THREADS>>>(deltas, keys);
    k_select<<<N_IMG * 2, K2_THREADS>>>(cls, deltas, gt, out, out_size);
}

// round 7
// speedup vs baseline: 6.8837x; 1.1822x over previous
#include <cuda_runtime.h>
#include <cstdint>

// ---------------- problem constants (fixed shapes) ----------------
#define N_IMG   8
#define K_ANC   9
#define HH      120
#define WW      120
#define M_GT    64
#define A_ANCH  (HH*WW*K_ANC)      /* 129600 */
#define HWSZ    (HH*WW)            /* 14400  */
#define IMG_SZ  1920.0f
#define KPOS    128
#define KNEG    60
#define CAP     4096                /* survivor capacity in shared */
#define TIE_CAP 128

// static pre-filter thresholds (float bit patterns; u >= T -> high tier)
#define TP_HI   0x3F400000u         /* 0.75      : keep ~1/4  of positives */
#define TN_HI   0x3F7C0000u         /* 0.984375  : keep ~1/64 of negatives */

// ---------------- static device scratch (no allocations) ----------------
__device__ uint2  g_pos[N_IMG * A_ANCH];   // low tier grows up, high tier grows down
__device__ uint2  g_neg[N_IMG * A_ANCH];
__device__ int    g_cnt[N_IMG * 4];        // [n][0]=pos_lo 1=pos_hi 2=neg_lo 3=neg_hi
__device__ float4 g_part[N_IMG][2];        // (bce, pred, l1, count)
__device__ int    g_ticket;                // zero-init; reset by last block

__constant__ float4 c_gt[N_IMG * M_GT];

struct Keys { unsigned kp0[N_IMG], kp1[N_IMG], kn0[N_IMG], kn1[N_IMG]; };

// ---------------- threefry2x32 (JAX-exact) ----------------
__host__ __device__ __forceinline__ unsigned rotl32(unsigned x, int d) {
    return (x << d) | (x >> (32 - d));
}
__host__ __device__ __forceinline__ void tf2x32(unsigned k0, unsigned k1,
                                                unsigned x0, unsigned x1,
                                                unsigned& o0, unsigned& o1) {
    unsigned ks2 = k0 ^ k1 ^ 0x1BD11BDAu;
    x0 += k0; x1 += k1;
#define TFR(r) { x0 += x1; x1 = rotl32(x1, r); x1 ^= x0; }
    TFR(13) TFR(15) TFR(26) TFR(6)   x0 += k1;  x1 += ks2 + 1u;
    TFR(17) TFR(29) TFR(16) TFR(24)  x0 += ks2; x1 += k0  + 2u;
    TFR(13) TFR(15) TFR(26) TFR(6)   x0 += k0;  x1 += k1  + 3u;
    TFR(17) TFR(29) TFR(16) TFR(24)  x0 += k1;  x1 += ks2 + 4u;
    TFR(13) TFR(15) TFR(26) TFR(6)   x0 += ks2; x1 += k0  + 5u;
#undef TFR
    o0 = x0; o1 = x1;
}

__device__ __forceinline__ unsigned ubits(unsigned k0, unsigned k1, int i) {
    unsigned o0, o1;
    tf2x32(k0, k1, 0u, (unsigned)i, o0, o1);
    unsigned b = o0 ^ o1;
    float u = __uint_as_float((b >> 9) | 0x3f800000u) - 1.0f;   // [0,1)
    return __float_as_uint(u);
}

// ---------------- geometry helpers ----------------
__device__ __forceinline__ void anchor_box(int k, int h, int w,
                                           float& ax1, float& ay1, float& ax2, float& ay2) {
    int r = k / 3, s = k % 3;
    float scale = (s == 0) ? 8.0f : ((s == 1) ? 16.0f : 32.0f);
    float sq2 = sqrtf(2.0f), sqh = sqrtf(0.5f);
    float srw = (r == 0) ? sq2 : ((r == 1) ? 1.0f : sqh);
    float srh = (r == 0) ? sqh : ((r == 1) ? 1.0f : sq2);
    float wsz = __fmul_rn(16.0f * scale, srw);
    float hsz = __fmul_rn(16.0f * scale, srh);
    float cx = __fmul_rn((float)w + 0.5f, 16.0f);
    float cy = __fmul_rn((float)h + 0.5f, 16.0f);
    float hw2 = __fmul_rn(wsz, 0.5f), hh2 = __fmul_rn(hsz, 0.5f);
    ax1 = __fsub_rn(cx, hw2); ay1 = __fsub_rn(cy, hh2);
    ax2 = __fadd_rn(cx, hw2); ay2 = __fadd_rn(cy, hh2);
}

__device__ __forceinline__ void region_box(const float* __restrict__ deltas,
                                           int n, int k, int h, int w,
                                           float ax1, float ay1, float ax2, float ay2,
                                           float& rx1, float& ry1, float& rx2, float& ry2) {
    int db = ((n * 4 * K_ANC + k * 4) * HH + h) * WW + w;
    rx1 = fminf(fmaxf(__fadd_rn(ax1, deltas[db          ]), 0.0f), IMG_SZ);
    ry1 = fminf(fmaxf(__fadd_rn(ay1, deltas[db +   HWSZ ]), 0.0f), IMG_SZ);
    rx2 = fminf(fmaxf(__fadd_rn(ax2, deltas[db + 2*HWSZ ]), 0.0f), IMG_SZ);
    ry2 = fminf(fmaxf(__fadd_rn(ay2, deltas[db + 3*HWSZ ]), 0.0f), IMG_SZ);
}

__device__ __forceinline__ int cls_index(int n, int a) {
    int k = a % K_ANC; int hw = a / K_ANC; int w = hw % WW; int h = hw / WW;
    return ((n * K_ANC + k) * HH + h) * WW + w;
}

__device__ __forceinline__ float softplusf(float x) {
    return fmaxf(x, 0.0f) + log1pf(expf(-fabsf(x)));
}
__device__ __forceinline__ float sl1(float d) {
    float ad = fabsf(d);
    return (ad < 0.1f) ? (0.5f * d * d / 0.1f) : (ad - 0.05f);
}

__device__ void pos_contrib(const float* __restrict__ cls, const float* __restrict__ deltas,
                            const float* __restrict__ gt, int n, int a, int m,
                            float& bce, float& pred, float& l1) {
    int k = a % K_ANC; int hw = a / K_ANC; int w = hw % WW; int h = hw / WW;
    float ax1, ay1, ax2, ay2;
    anchor_box(k, h, w, ax1, ay1, ax2, ay2);
    float rx1, ry1, rx2, ry2;
    region_box(deltas, n, k, h, w, ax1, ay1, ax2, ay2, rx1, ry1, rx2, ry2);
    float aw = __fsub_rn(ax2, ax1), ah = __fsub_rn(ay2, ay1);
    float acx = ax1 + 0.5f * aw, acy = ay1 + 0.5f * ah;
    float bw = fmaxf(__fsub_rn(rx2, rx1), 1e-6f), bh = fmaxf(__fsub_rn(ry2, ry1), 1e-6f);
    float bcx = rx1 + 0.5f * bw, bcy = ry1 + 0.5f * bh;
    float tp0 = (bcx - acx) / aw, tp1 = (bcy - acy) / ah;
    float tp2 = logf(bw / aw),    tp3 = logf(bh / ah);
    const float* g = gt + (n * M_GT + m) * 4;
    float gw = fmaxf(__fsub_rn(g[2], g[0]), 1e-6f), gh = fmaxf(__fsub_rn(g[3], g[1]), 1e-6f);
    float gcx = g[0] + 0.5f * gw, gcy = g[1] + 0.5f * gh;
    float tg0 = (gcx - acx) / aw, tg1 = (gcy - acy) / ah;
    float tg2 = logf(gw / aw),    tg3 = logf(gh / ah);
    l1 += sl1(tp0 - tg0) + sl1(tp1 - tg1) + sl1(tp2 - tg2) + sl1(tp3 - tg3);
    float x = cls[((n * K_ANC + k) * HH + h) * WW + w];
    bce += softplusf(-x); pred += x;
}

// ---------------- kernel 1: region + IoU match + tiered compaction ----------------
#define K1_THREADS 320
__global__ __launch_bounds__(K1_THREADS) void k_match(
        const float* __restrict__ deltas, Keys keys) {
    int n = blockIdx.y;
    __shared__ float4 sg[M_GT];
    __shared__ int    scnt[4];
    __shared__ int    sbase[4];
    __shared__ int    wboff[K1_THREADS / 32][4];
    int tid = threadIdx.x;
    if (tid < M_GT) sg[tid] = c_gt[n * M_GT + tid];
    if (tid < 4) scnt[tid] = 0;
    __syncthreads();

    int t = blockIdx.x * K1_THREADS + tid;
    int k = t / HWSZ; int hw = t % HWSZ; int h = hw / WW; int w = hw % WW;
    int a = hw * K_ANC + k;

    float ax1, ay1, ax2, ay2;
    anchor_box(k, h, w, ax1, ay1, ax2, ay2);
    float rx1, ry1, rx2, ry2;
    region_box(deltas, n, k, h, w, ax1, ay1, ax2, ay2, rx1, ry1, rx2, ry2);
    float ab = __fmul_rn(fmaxf(__fsub_rn(rx2, rx1), 0.0f),
                         fmaxf(__fsub_rn(ry2, ry1), 0.0f));

    // warp-union bbox (skipped GTs provably have inter == 0 for every lane)
    float wx1 = rx1, wy1 = ry1, wx2 = rx2, wy2 = ry2;
#pragma unroll
    for (int o = 16; o > 0; o >>= 1) {
        wx1 = fminf(wx1, __shfl_xor_sync(0xffffffffu, wx1, o));
        wy1 = fminf(wy1, __shfl_xor_sync(0xffffffffu, wy1, o));
        wx2 = fmaxf(wx2, __shfl_xor_sync(0xffffffffu, wx2, o));
        wy2 = fmaxf(wy2, __shfl_xor_sync(0xffffffffu, wy2, o));
    }

    // ballot-compacted survivor masks: lane tests GT[lane] and GT[lane+32]
    int lane = tid & 31;
    float4 gA = sg[lane];
    float4 gB = sg[lane + 32];
    bool oA = (wx2 > gA.x) && (gA.z > wx1) && (wy2 > gA.y) && (gA.w > wy1);
    bool oB = (wx2 > gB.x) && (gB.z > wx1) && (wy2 > gB.y) && (gB.w > wy1);
    unsigned mA = __ballot_sync(0xffffffffu, oA);
    unsigned mB = __ballot_sync(0xffffffffu, oB);

    float best = 0.0f; int arg = 0;
    const float4* gbase = &c_gt[n * M_GT];
    unsigned mm = mA; int mofs = 0;
#pragma unroll 1
    for (int half = 0; half < 2; half++) {
        while (mm) {
            int m = (__ffs(mm) - 1) + mofs;        // increasing m: first-tie preserved
            mm &= mm - 1;
            float4 g = gbase[m];                   // uniform -> const port
            float ag = __fmul_rn(fmaxf(__fsub_rn(g.z, g.x), 0.0f),
                                 fmaxf(__fsub_rn(g.w, g.y), 0.0f));
            float ix1 = fmaxf(rx1, g.x), iy1 = fmaxf(ry1, g.y);
            float ix2 = fminf(rx2, g.z), iy2 = fminf(ry2, g.w);
            float inter = __fmul_rn(fmaxf(__fsub_rn(ix2, ix1), 0.0f),
                                    fmaxf(__fsub_rn(iy2, iy1), 0.0f));
            float den = __fadd_rn(__fsub_rn(__fadd_rn(ab, ag), inter), 1e-6f);
            if (inter > __fmul_rn(__fmul_rn(best, den), 0.9999995f) && inter > 0.0f) {
                float iou = __fdiv_rn(inter, den);
                if (iou > best) { best = iou; arg = m; }
            }
        }
        mm = mB; mofs = 32;
    }

    int match = (best >= 0.4f) ? arg : ((best < 0.1f) ? -1 : -2);
    unsigned ub = 0u;
    if (match >= 0)       ub = ubits(keys.kp0[n], keys.kp1[n], a);
    else if (match == -1) ub = ubits(keys.kn0[n], keys.kn1[n], a);
    bool isp = (match >= 0) && (ub != 0u);
    bool isn = (match == -1) && (ub != 0u);
    bool hip = isp && (ub >= TP_HI);
    bool hin = isn && (ub >= TN_HI);

    int wid = tid >> 5;
    unsigned m0 = __ballot_sync(0xffffffffu, isp && !hip);
    unsigned m1 = __ballot_sync(0xffffffffu, hip);
    unsigned m2 = __ballot_sync(0xffffffffu, isn && !hin);
    unsigned m3 = __ballot_sync(0xffffffffu, hin);
    if (lane == 0) {
        wboff[wid][0] = atomicAdd(&scnt[0], __popc(m0));
        wboff[wid][1] = atomicAdd(&scnt[1], __popc(m1));
        wboff[wid][2] = atomicAdd(&scnt[2], __popc(m2));
        wboff[wid][3] = atomicAdd(&scnt[3], __popc(m3));
    }
    __syncthreads();
    if (tid < 4) sbase[tid] = atomicAdd(&g_cnt[n * 4 + tid], scnt[tid]);
    __syncthreads();
    unsigned lm = (1u << lane) - 1u;
    if (isp) {
        uint2 e = make_uint2(ub, (unsigned)a | ((unsigned)arg << 17));
        if (hip) {
            int p = sbase[1] + wboff[wid][1] + __popc(m1 & lm);
            g_pos[n * A_ANCH + (A_ANCH - 1 - p)] = e;
        } else {
            int p = sbase[0] + wboff[wid][0] + __popc(m0 & lm);
            g_pos[n * A_ANCH + p] = e;
        }
    }
    if (isn) {
        uint2 e = make_uint2(ub, (unsigned)a);
        if (hin) {
            int p = sbase[3] + wboff[wid][3] + __popc(m3 & lm);
            g_neg[n * A_ANCH + (A_ANCH - 1 - p)] = e;
        } else {
            int p = sbase[2] + wboff[wid][2] + __popc(m2 & lm);
            g_neg[n * A_ANCH + p] = e;
        }
    }
}

// ---------------- kernel 2: exact top-K via radix select + loss reduce ----------------
#define K2_THREADS 512
#define K2_WARPS   (K2_THREADS / 32)

__global__ __launch_bounds__(K2_THREADS) void k_select(
        const float* __restrict__ cls, const float* __restrict__ deltas,
        const float* __restrict__ gt, float* out, int out_size) {
    int bx = blockIdx.x;
    int n = bx >> 1, cat = bx & 1;                 // 0 = pos, 1 = neg
    int tid = threadIdx.x;
    int wid = tid >> 5, lane = tid & 31;
    const uint2* base = (cat ? g_neg : g_pos) + n * A_ANCH;

    __shared__ int sClo, sChi;
    if (tid == 0) {
        sClo = g_cnt[n * 4 + cat * 2 + 0];
        sChi = g_cnt[n * 4 + cat * 2 + 1];
        g_cnt[n * 4 + cat * 2 + 0] = 0;            // single-owner read+reset
        g_cnt[n * 4 + cat * 2 + 1] = 0;
    }
    __syncthreads();
    int Clo = sClo, Chi = sChi;
    int Ctot = Clo + Chi;
    int K = cat ? KNEG : KPOS;
    int need = min(K, Ctot);

    // segment view: high tier always; low tier only when high can't cover top-K
    const uint2* segA = base + (A_ANCH - Chi);
    int LA = Chi;
    int LB = (Chi >= need) ? 0 : Clo;
    int L = LA + LB;
    auto LD = [&](int i) -> uint2 { return (i < LA) ? segA[i] : base[i - LA]; };

    __shared__ uint2    ss[CAP];
    __shared__ unsigned stie[TIE_CAP];
    __shared__ int      swarp[K2_WARPS];
    __shared__ int      swbase[K2_WARPS];
    __shared__ float    fwarp[K2_WARPS][3];
    __shared__ int      stot[3];
    __shared__ unsigned sT;
    __shared__ int      sS, sLo, sHi, sFlag;
    __shared__ int      hist[256];
    __shared__ unsigned s_sel;
    __shared__ int      s_needr, s_tiecnt;

    unsigned T0 = 1u, T1 = 1u;
    {
        float invC = 1.0f / (float)max(Ctot, 1);
        float u0 = 1.0f - (float)(2 * K) * invC;
        float u1 = 1.0f - (float)(8 * K) * invC;
        T0 = (u0 <= 0.0f) ? 1u : __float_as_uint(u0);
        T1 = (u1 <= 0.0f) ? 1u : __float_as_uint(u1);
    }

    // ---- pass 1: counts only ----
    int c0 = 0, c1 = 0, c2 = 0;
    for (int i = tid; i < L; i += K2_THREADS) {
        unsigned v = LD(i).x;
        c0 += (v >= T0); c1 += (v >= T1); c2++;
    }
#pragma unroll
    for (int o = 16; o > 0; o >>= 1) {
        c0 += __shfl_down_sync(0xffffffffu, c0, o);
        c1 += __shfl_down_sync(0xffffffffu, c1, o);
        c2 += __shfl_down_sync(0xffffffffu, c2, o);
    }
    if (lane == 0) { swarp[wid] = c0; }
    __syncthreads();
    if (tid == 0) { int s = 0; for (int q = 0; q < K2_WARPS; q++) s += swarp[q]; stot[0] = s; }
    __syncthreads();
    if (lane == 0) { swarp[wid] = c1; }
    __syncthreads();
    if (tid == 0) { int s = 0; for (int q = 0; q < K2_WARPS; q++) s += swarp[q]; stot[1] = s; }
    __syncthreads();
    if (lane == 0) { swarp[wid] = c2; }
    __syncthreads();
    if (tid == 0) { int s = 0; for (int q = 0; q < K2_WARPS; q++) s += swarp[q]; stot[2] = s; }
    __syncthreads();

    // ---- choose threshold T with count in [need, CAP] ----
    unsigned T; int S;
    if (stot[0] >= need && stot[0] <= CAP)      { T = T0; S = stot[0]; }
    else if (stot[1] >= need && stot[1] <= CAP) { T = T1; S = stot[1]; }
    else if (stot[2] <= CAP)                    { T = 1u; S = stot[2]; }
    else {
        // exactness backstop: binary search tightest threshold with count in [need, CAP]
        if (tid == 0) {
            if (stot[1] >= need) { sLo = (int)T1; sHi = (int)T0; sT = T1; sS = stot[1]; }
            else                 { sLo = (int)1u; sHi = (int)T1; sT = 1u; sS = stot[2]; }
            sFlag = 1;
        }
        __syncthreads();
        for (int iter = 0; iter < 34 && sFlag; iter++) {
            unsigned lo = (unsigned)sLo, hi = (unsigned)sHi;
            if (hi - lo <= 1u) break;
            unsigned mid = lo + ((hi - lo) >> 1);
            int c = 0;
            for (int i = tid; i < L; i += K2_THREADS) c += (LD(i).x >= mid);
#pragma unroll
            for (int o = 16; o > 0; o >>= 1) c += __shfl_down_sync(0xffffffffu, c, o);
            if (lane == 0) swarp[wid] = c;
            __syncthreads();
            if (tid == 0) {
                int s = 0;
                for (int q = 0; q < K2_WARPS; q++) s += swarp[q];
                if (s >= need) { sLo = (int)mid; sT = mid; sS = s; }
                else           { sHi = (int)mid; }
                if (sS <= CAP) sFlag = 0;
            }
            __syncthreads();
        }
        __syncthreads();
        T = sT; S = min(sS, CAP);
    }
    __syncthreads();

    // ---- pass 2: deterministic capture (count -> block scan -> place) ----
    int kt = 0;
    for (int i = tid; i < L; i += K2_THREADS) kt += (LD(i).x >= T);
    int inc = kt;
#pragma unroll
    for (int o = 1; o < 32; o <<= 1) {
        int v = __shfl_up_sync(0xffffffffu, inc, o);
        if (lane >= o) inc += v;
    }
    if (lane == 31) swarp[wid] = inc;
    __syncthreads();
    if (tid == 0) {
        int run = 0;
        for (int q = 0; q < K2_WARPS; q++) { int v = swarp[q]; swbase[q] = run; run += v; }
    }
    __syncthreads();
    int off = swbase[wid] + (inc - kt);
    for (int i = tid; i < L; i += K2_THREADS) {
        uint2 e = LD(i);
        if (e.x >= T) { if (off < CAP) ss[off] = e; off++; }
    }
    if (tid == 0) { s_sel = 0u; s_needr = need; s_tiecnt = 0; }
    __syncthreads();

    // ---- radix select: exact k-th largest value among S captured ----
#pragma unroll 1
    for (int p = 0; p < 4; p++) {
        int shift = 24 - 8 * p;
        if (tid < 256) hist[tid] = 0;
        __syncthreads();
        unsigned selhi = s_sel;
        int nr = s_needr;
        for (int j = tid; j < S; j += K2_THREADS) {
            unsigned v = ss[j].x;
            if (p == 0 || (v >> (shift + 8)) == (selhi >> (shift + 8)))
                atomicAdd(&hist[(v >> shift) & 0xFFu], 1);
        }
        __syncthreads();
        if (wid == 0 && nr > 0) {
            int bbase = 255 - 8 * lane;            // lane covers 8 bins, descending
            int ch = 0;
#pragma unroll
            for (int q = 0; q < 8; q++) ch += hist[bbase - q];
            int pre = ch;
#pragma unroll
            for (int o = 1; o < 32; o <<= 1) {
                int v = __shfl_up_sync(0xffffffffu, pre, o);
                if (lane >= o) pre += v;
            }
            int excl = pre - ch;
            if (excl < nr && nr <= pre) {
                int tgt = nr - excl, cum = 0;
                for (int q = 0; q < 8; q++) {
                    int c = hist[bbase - q];
                    if (cum + c >= tgt) {
                        s_sel = selhi | ((unsigned)(bbase - q) << shift);
                        s_needr = tgt - cum;
                        break;
                    }
                    cum += c;
                }
            }
        }
        __syncthreads();
    }
    unsigned Tk = s_sel;
    int r = s_needr;                               // ties at boundary to take

    // ---- gather boundary ties, sort by anchor index (lowest first) ----
    for (int j = tid; j < S; j += K2_THREADS) {
        if (ss[j].x == Tk) {
            int p = atomicAdd(&s_tiecnt, 1);
            if (p < TIE_CAP) stie[p] = ss[j].y;
        }
    }
    __syncthreads();
    if (tid == 0 && need > 0) {
        int c = min(s_tiecnt, TIE_CAP);
        for (int i = 1; i < c; i++) {              // insertion sort by a = y & 0x1FFFF
            unsigned key = stie[i]; int j = i - 1;
            while (j >= 0 && (stie[j] & 0x1FFFFu) > (key & 0x1FFFFu)) {
                stie[j + 1] = stie[j]; j--;
            }
            stie[j + 1] = key;
        }
    }
    __syncthreads();

    // ---- order-free accumulation: all v > Tk, plus first r ties ----
    float b = 0.0f, p = 0.0f, l = 0.0f;
    if (need > 0) {
        for (int j = tid; j < S; j += K2_THREADS) {
            uint2 e = ss[j];
            if (e.x > Tk) {
                int a = (int)(e.y & 0x1FFFFu);
                if (cat) {
                    float x = cls[cls_index(n, a)];
                    b += softplusf(x); p += x;
                } else {
                    int m = (int)(e.y >> 17);
                    pos_contrib(cls, deltas, gt, n, a, m, b, p, l);
                }
            }
        }
        if (tid < r) {
            unsigned y = stie[tid];
            int a = (int)(y & 0x1FFFFu);
            if (cat) {
                float x = cls[cls_index(n, a)];
                b += softplusf(x); p += x;
            } else {
                int m = (int)(y >> 17);
                pos_contrib(cls, deltas, gt, n, a, m, b, p, l);
            }
        }
    }
#pragma unroll
    for (int o = 16; o > 0; o >>= 1) {
        b += __shfl_down_sync(0xffffffffu, b, o);
        p += __shfl_down_sync(0xffffffffu, p, o);
        l += __shfl_down_sync(0xffffffffu, l, o);
    }
    if (lane == 0) { fwarp[wid][0] = b; fwarp[wid][1] = p; fwarp[wid][2] = l; }
    __syncthreads();

    if (tid == 0) {
        float sb = 0.f, sp = 0.f, sl_ = 0.f;
        for (int q = 0; q < K2_WARPS; q++) {
            sb += fwarp[q][0]; sp += fwarp[q][1]; sl_ += fwarp[q][2];
        }
        g_part[n][cat] = make_float4(sb, sp, sl_, (float)need);
        __threadfence();
        int ticket = atomicAdd(&g_ticket, 1);
        if (ticket == N_IMG * 2 - 1) {
            __threadfence();
            float cl = 0.f, bl = 0.f, fg = 0.f, bg = 0.f, pm = 0.f;
            for (int q = 0; q < N_IMG; q++) {
                volatile float* Pp = (volatile float*)&g_part[q][0];
                volatile float* Gg = (volatile float*)&g_part[q][1];
                float Pb = Pp[0], Pd = Pp[1], Pl = Pp[2], np = Pp[3];
                float Gb = Gg[0], Gd = Gg[1], nn = Gg[3];
                float denom = fmaxf(np + nn, 1.0f);
                cl += (Pb + Gb) / denom;
                bl += Pl / (fmaxf(np, 1.0f) * (float)N_IMG);
                fg += np; bg += nn;
                if (q == N_IMG - 1) pm = (Pd + Gd) / denom;
            }
            out[0] = cl; out[1] = bl; out[2] = bg; out[3] = fg; out[4] = pm;
            for (int i = 5; i < out_size; i++) out[i] = 0.0f;
            g_ticket = 0;
        }
    }
}

// ---------------- host launcher ----------------
extern "C" void kernel_launch(void* const* d_in, const int* in_sizes, int n_in,
                              void* d_out, int out_size) {
    (void)in_sizes; (void)n_in;
    const float* cls    = (const float*)d_in[0];
    const float* deltas = (const float*)d_in[1];
    const float* gt     = (const float*)d_in[2];
    float* out = (float*)d_out;

    Keys keys;
    for (int n = 0; n < N_IMG; n++) {
        unsigned K0, K1;
        tf2x32(0u, 42u, 0u, (unsigned)n, K0, K1);
        unsigned p0, p1, q0, q1;
        tf2x32(K0, K1, 0u, 0u, p0, p1);
        tf2x32(K0, K1, 0u, 1u, q0, q1);
        keys.kp0[n] = p0; keys.kp1[n] = p1;
        keys.kn0[n] = q0; keys.kn1[n] = q1;
    }

    cudaMemcpyToSymbolAsync(c_gt, gt, N_IMG * M_GT * sizeof(float4), 0,
                            cudaMemcpyDeviceToDevice, 0);

    dim3 g1(A_ANCH / K1_THREADS, N_IMG);                   // 405 x 8
    k_match<<<g1, K1_THREADS>>>(deltas, keys);
    k_select<<<N_IMG * 2, K2_THREADS>>>(cls, deltas, gt, out, out_size);
}

// round 8
// speedup vs baseline: 7.1040x; 1.0320x over previous
#include <cuda_runtime.h>
#include <cstdint>

// ---------------- problem constants (fixed shapes) ----------------
#define N_IMG   8
#define K_ANC   9
#define HH      120
#define WW      120
#define M_GT    64
#define A_ANCH  (HH*WW*K_ANC)      /* 129600 */
#define HWSZ    (HH*WW)            /* 14400  */
#define IMG_SZ  1920.0f
#define KPOS    128
#define KNEG    60
#define CAP     4096                /* survivor capacity in shared */
#define TIE_CAP 128

// static pre-filter thresholds (float bit patterns; u >= T -> high tier)
#define TP_HI   0x3F400000u         /* 0.75      : keep ~1/4  of positives */
#define TN_HI   0x3F7C0000u         /* 0.984375  : keep ~1/64 of negatives */

// ---------------- static device scratch (no allocations) ----------------
__device__ uint2  g_pos[N_IMG * A_ANCH];   // low tier grows up, high tier grows down
__device__ uint2  g_neg[N_IMG * A_ANCH];
__device__ int    g_cnt[N_IMG * 4];        // [n][0]=pos_lo 1=pos_hi 2=neg_lo 3=neg_hi
__device__ float4 g_part[N_IMG][2];        // (bce, pred, l1, count)
__device__ int    g_ticket;                // zero-init; reset by last block

__constant__ float4 c_gt[N_IMG * M_GT];

struct Keys { unsigned kp0[N_IMG], kp1[N_IMG], kn0[N_IMG], kn1[N_IMG]; };

// ---------------- threefry2x32 (JAX-exact) ----------------
__host__ __device__ __forceinline__ unsigned rotl32(unsigned x, int d) {
    return (x << d) | (x >> (32 - d));
}
__host__ __device__ __forceinline__ void tf2x32(unsigned k0, unsigned k1,
                                                unsigned x0, unsigned x1,
                                                unsigned& o0, unsigned& o1) {
    unsigned ks2 = k0 ^ k1 ^ 0x1BD11BDAu;
    x0 += k0; x1 += k1;
#define TFR(r) { x0 += x1; x1 = rotl32(x1, r); x1 ^= x0; }
    TFR(13) TFR(15) TFR(26) TFR(6)   x0 += k1;  x1 += ks2 + 1u;
    TFR(17) TFR(29) TFR(16) TFR(24)  x0 += ks2; x1 += k0  + 2u;
    TFR(13) TFR(15) TFR(26) TFR(6)   x0 += k0;  x1 += k1  + 3u;
    TFR(17) TFR(29) TFR(16) TFR(24)  x0 += k1;  x1 += ks2 + 4u;
    TFR(13) TFR(15) TFR(26) TFR(6)   x0 += ks2; x1 += k0  + 5u;
#undef TFR
    o0 = x0; o1 = x1;
}

__device__ __forceinline__ unsigned ubits(unsigned k0, unsigned k1, int i) {
    unsigned o0, o1;
    tf2x32(k0, k1, 0u, (unsigned)i, o0, o1);
    unsigned b = o0 ^ o1;
    float u = __uint_as_float((b >> 9) | 0x3f800000u) - 1.0f;   // [0,1)
    return __float_as_uint(u);
}

// ---------------- geometry helpers ----------------
__device__ __forceinline__ void anchor_box(int k, int h, int w,
                                           float& ax1, float& ay1, float& ax2, float& ay2) {
    int r = k / 3, s = k % 3;
    float scale = (s == 0) ? 8.0f : ((s == 1) ? 16.0f : 32.0f);
    float sq2 = sqrtf(2.0f), sqh = sqrtf(0.5f);
    float srw = (r == 0) ? sq2 : ((r == 1) ? 1.0f : sqh);
    float srh = (r == 0) ? sqh : ((r == 1) ? 1.0f : sq2);
    float wsz = __fmul_rn(16.0f * scale, srw);
    float hsz = __fmul_rn(16.0f * scale, srh);
    float cx = __fmul_rn((float)w + 0.5f, 16.0f);
    float cy = __fmul_rn((float)h + 0.5f, 16.0f);
    float hw2 = __fmul_rn(wsz, 0.5f), hh2 = __fmul_rn(hsz, 0.5f);
    ax1 = __fsub_rn(cx, hw2); ay1 = __fsub_rn(cy, hh2);
    ax2 = __fadd_rn(cx, hw2); ay2 = __fadd_rn(cy, hh2);
}

__device__ __forceinline__ void region_box(const float* __restrict__ deltas,
                                           int n, int k, int h, int w,
                                           float ax1, float ay1, float ax2, float ay2,
                                           float& rx1, float& ry1, float& rx2, float& ry2) {
    int db = ((n * 4 * K_ANC + k * 4) * HH + h) * WW + w;
    rx1 = fminf(fmaxf(__fadd_rn(ax1, deltas[db          ]), 0.0f), IMG_SZ);
    ry1 = fminf(fmaxf(__fadd_rn(ay1, deltas[db +   HWSZ ]), 0.0f), IMG_SZ);
    rx2 = fminf(fmaxf(__fadd_rn(ax2, deltas[db + 2*HWSZ ]), 0.0f), IMG_SZ);
    ry2 = fminf(fmaxf(__fadd_rn(ay2, deltas[db + 3*HWSZ ]), 0.0f), IMG_SZ);
}

__device__ __forceinline__ int cls_index(int n, int a) {
    int k = a % K_ANC; int hw = a / K_ANC; int w = hw % WW; int h = hw / WW;
    return ((n * K_ANC + k) * HH + h) * WW + w;
}

__device__ __forceinline__ float softplusf(float x) {
    return fmaxf(x, 0.0f) + log1pf(expf(-fabsf(x)));
}
__device__ __forceinline__ float sl1(float d) {
    float ad = fabsf(d);
    return (ad < 0.1f) ? (0.5f * d * d / 0.1f) : (ad - 0.05f);
}

__device__ void pos_contrib(const float* __restrict__ cls, const float* __restrict__ deltas,
                            const float* __restrict__ gt, int n, int a, int m,
                            float& bce, float& pred, float& l1) {
    int k = a % K_ANC; int hw = a / K_ANC; int w = hw % WW; int h = hw / WW;
    float ax1, ay1, ax2, ay2;
    anchor_box(k, h, w, ax1, ay1, ax2, ay2);
    float rx1, ry1, rx2, ry2;
    region_box(deltas, n, k, h, w, ax1, ay1, ax2, ay2, rx1, ry1, rx2, ry2);
    float aw = __fsub_rn(ax2, ax1), ah = __fsub_rn(ay2, ay1);
    float acx = ax1 + 0.5f * aw, acy = ay1 + 0.5f * ah;
    float bw = fmaxf(__fsub_rn(rx2, rx1), 1e-6f), bh = fmaxf(__fsub_rn(ry2, ry1), 1e-6f);
    float bcx = rx1 + 0.5f * bw, bcy = ry1 + 0.5f * bh;
    float tp0 = (bcx - acx) / aw, tp1 = (bcy - acy) / ah;
    float tp2 = logf(bw / aw),    tp3 = logf(bh / ah);
    const float* g = gt + (n * M_GT + m) * 4;
    float gw = fmaxf(__fsub_rn(g[2], g[0]), 1e-6f), gh = fmaxf(__fsub_rn(g[3], g[1]), 1e-6f);
    float gcx = g[0] + 0.5f * gw, gcy = g[1] + 0.5f * gh;
    float tg0 = (gcx - acx) / aw, tg1 = (gcy - acy) / ah;
    float tg2 = logf(gw / aw),    tg3 = logf(gh / ah);
    l1 += sl1(tp0 - tg0) + sl1(tp1 - tg1) + sl1(tp2 - tg2) + sl1(tp3 - tg3);
    float x = cls[((n * K_ANC + k) * HH + h) * WW + w];
    bce += softplusf(-x); pred += x;
}

// ---------------- kernel 1: region + IoU match + tiered compaction ----------------
#define K1_THREADS 320
__global__ __launch_bounds__(K1_THREADS) void k_match(
        const float* __restrict__ deltas, Keys keys) {
    int n = blockIdx.y;
    __shared__ float4 sg[M_GT];
    __shared__ float  sag[M_GT];
    __shared__ int    scnt[4];
    __shared__ int    sbase[4];
    __shared__ int    wboff[K1_THREADS / 32][4];
    int tid = threadIdx.x;
    if (tid < M_GT) {
        float4 b = c_gt[n * M_GT + tid];
        sg[tid] = b;
        sag[tid] = __fmul_rn(fmaxf(__fsub_rn(b.z, b.x), 0.0f),
                             fmaxf(__fsub_rn(b.w, b.y), 0.0f));
    }
    if (tid < 4) scnt[tid] = 0;
    __syncthreads();

    int t = blockIdx.x * K1_THREADS + tid;
    int k = t / HWSZ; int hw = t % HWSZ; int h = hw / WW; int w = hw % WW;
    int a = hw * K_ANC + k;

    float ax1, ay1, ax2, ay2;
    anchor_box(k, h, w, ax1, ay1, ax2, ay2);
    float rx1, ry1, rx2, ry2;
    region_box(deltas, n, k, h, w, ax1, ay1, ax2, ay2, rx1, ry1, rx2, ry2);
    float ab = __fmul_rn(fmaxf(__fsub_rn(rx2, rx1), 0.0f),
                         fmaxf(__fsub_rn(ry2, ry1), 0.0f));

    // warp-union bbox (skipped GTs provably have inter == 0 for every lane)
    float wx1 = rx1, wy1 = ry1, wx2 = rx2, wy2 = ry2;
#pragma unroll
    for (int o = 16; o > 0; o >>= 1) {
        wx1 = fminf(wx1, __shfl_xor_sync(0xffffffffu, wx1, o));
        wy1 = fminf(wy1, __shfl_xor_sync(0xffffffffu, wy1, o));
        wx2 = fmaxf(wx2, __shfl_xor_sync(0xffffffffu, wx2, o));
        wy2 = fmaxf(wy2, __shfl_xor_sync(0xffffffffu, wy2, o));
    }

    // ballot-compacted survivor masks: lane tests GT[lane] and GT[lane+32]
    int lane = tid & 31;
    float4 gA = sg[lane];
    float4 gB = sg[lane + 32];
    bool oA = (wx2 > gA.x) && (gA.z > wx1) && (wy2 > gA.y) && (gA.w > wy1);
    bool oB = (wx2 > gB.x) && (gB.z > wx1) && (wy2 > gB.y) && (gB.w > wy1);
    unsigned mA = __ballot_sync(0xffffffffu, oA);
    unsigned mB = __ballot_sync(0xffffffffu, oB);

    float best = 0.0f; int arg = 0;
    const float4* gbase = &c_gt[n * M_GT];
    unsigned mm = mA; int mofs = 0;
#pragma unroll 1
    for (int half = 0; half < 2; half++) {
        while (mm) {
            int m = (__ffs(mm) - 1) + mofs;        // increasing m: first-tie preserved
            mm &= mm - 1;
            float4 g = gbase[m];                   // uniform -> const port
            float ix1 = fmaxf(rx1, g.x), iy1 = fmaxf(ry1, g.y);
            float ix2 = fminf(rx2, g.z), iy2 = fminf(ry2, g.w);
            float inter = __fmul_rn(fmaxf(__fsub_rn(ix2, ix1), 0.0f),
                                    fmaxf(__fsub_rn(iy2, iy1), 0.0f));
            float den = __fadd_rn(__fsub_rn(__fadd_rn(ab, sag[m]), inter), 1e-6f);
            if (inter > __fmul_rn(__fmul_rn(best, den), 0.9999995f) && inter > 0.0f) {
                float iou = __fdiv_rn(inter, den);
                if (iou > best) { best = iou; arg = m; }
            }
        }
        mm = mB; mofs = 32;
    }

    int match = (best >= 0.4f) ? arg : ((best < 0.1f) ? -1 : -2);
    unsigned ub = 0u;
    if (match >= 0)       ub = ubits(keys.kp0[n], keys.kp1[n], a);
    else if (match == -1) ub = ubits(keys.kn0[n], keys.kn1[n], a);
    bool isp = (match >= 0) && (ub != 0u);
    bool isn = (match == -1) && (ub != 0u);
    bool hip = isp && (ub >= TP_HI);
    bool hin = isn && (ub >= TN_HI);

    int wid = tid >> 5;
    unsigned m0 = __ballot_sync(0xffffffffu, isp && !hip);
    unsigned m1 = __ballot_sync(0xffffffffu, hip);
    unsigned m2 = __ballot_sync(0xffffffffu, isn && !hin);
    unsigned m3 = __ballot_sync(0xffffffffu, hin);
    if (lane == 0) {
        wboff[wid][0] = atomicAdd(&scnt[0], __popc(m0));
        wboff[wid][1] = atomicAdd(&scnt[1], __popc(m1));
        wboff[wid][2] = atomicAdd(&scnt[2], __popc(m2));
        wboff[wid][3] = atomicAdd(&scnt[3], __popc(m3));
    }
    __syncthreads();
    if (tid < 4) sbase[tid] = atomicAdd(&g_cnt[n * 4 + tid], scnt[tid]);
    __syncthreads();
    unsigned lm = (1u << lane) - 1u;
    if (isp) {
        uint2 e = make_uint2(ub, (unsigned)a | ((unsigned)arg << 17));
        if (hip) {
            int p = sbase[1] + wboff[wid][1] + __popc(m1 & lm);
            g_pos[n * A_ANCH + (A_ANCH - 1 - p)] = e;
        } else {
            int p = sbase[0] + wboff[wid][0] + __popc(m0 & lm);
            g_pos[n * A_ANCH + p] = e;
        }
    }
    if (isn) {
        uint2 e = make_uint2(ub, (unsigned)a);
        if (hin) {
            int p = sbase[3] + wboff[wid][3] + __popc(m3 & lm);
            g_neg[n * A_ANCH + (A_ANCH - 1 - p)] = e;
        } else {
            int p = sbase[2] + wboff[wid][2] + __popc(m2 & lm);
            g_neg[n * A_ANCH + p] = e;
        }
    }
}

// ---------------- kernel 2: exact top-K via radix select + loss reduce ----------------
#define K2_THREADS 512
#define K2_WARPS   (K2_THREADS / 32)

__global__ __launch_bounds__(K2_THREADS) void k_select(
        const float* __restrict__ cls, const float* __restrict__ deltas,
        const float* __restrict__ gt, float* out, int out_size) {
    int bx = blockIdx.x;
    int n = bx >> 1, cat = bx & 1;                 // 0 = pos, 1 = neg
    int tid = threadIdx.x;
    int wid = tid >> 5, lane = tid & 31;
    const uint2* base = (cat ? g_neg : g_pos) + n * A_ANCH;

    __shared__ int sClo, sChi;
    if (tid == 0) {
        sClo = g_cnt[n * 4 + cat * 2 + 0];
        sChi = g_cnt[n * 4 + cat * 2 + 1];
        g_cnt[n * 4 + cat * 2 + 0] = 0;            // single-owner read+reset
        g_cnt[n * 4 + cat * 2 + 1] = 0;
    }
    __syncthreads();
    int Clo = sClo, Chi = sChi;
    int Ctot = Clo + Chi;
    int K = cat ? KNEG : KPOS;
    int need = min(K, Ctot);

    // segment view: high tier always; low tier only when high can't cover top-K
    const uint2* segA = base + (A_ANCH - Chi);
    int LA = Chi;
    int LB = (Chi >= need) ? 0 : Clo;
    int L = LA + LB;
    auto LD = [&](int i) -> uint2 { return (i < LA) ? segA[i] : base[i - LA]; };

    __shared__ uint2    ss[CAP];
    __shared__ unsigned stie[TIE_CAP];
    __shared__ int      swarp[K2_WARPS][3];
    __shared__ float    fwarp[K2_WARPS][3];
    __shared__ int      stot[3];
    __shared__ unsigned sT;
    __shared__ int      sS, sLo, sHi, sFlag;
    __shared__ int      hist[256];
    __shared__ unsigned s_sel;
    __shared__ int      s_needr, s_tiecnt, scap;

    unsigned T0 = 1u, T1 = 1u;
    {
        float invC = 1.0f / (float)max(Ctot, 1);
        float u0 = 1.0f - (float)(2 * K) * invC;
        float u1 = 1.0f - (float)(8 * K) * invC;
        T0 = (u0 <= 0.0f) ? 1u : __float_as_uint(u0);
        T1 = (u1 <= 0.0f) ? 1u : __float_as_uint(u1);
    }
    if (tid == 0) scap = 0;
    __syncthreads();

    // ---- single scan: 3 counts + opportunistic atomic capture at T0 ----
    int c0 = 0, c1 = 0, c2 = 0;
    for (int i = tid; i < L; i += K2_THREADS) {
        uint2 e = LD(i);
        unsigned v = e.x;
        c0 += (v >= T0); c1 += (v >= T1); c2++;
        if (v >= T0) {
            int p = atomicAdd(&scap, 1);
            if (p < CAP) ss[p] = e;                // order-free: radix hist + tie sort
        }
    }
#pragma unroll
    for (int o = 16; o > 0; o >>= 1) {
        c0 += __shfl_down_sync(0xffffffffu, c0, o);
        c1 += __shfl_down_sync(0xffffffffu, c1, o);
        c2 += __shfl_down_sync(0xffffffffu, c2, o);
    }
    if (lane == 0) { swarp[wid][0] = c0; swarp[wid][1] = c1; swarp[wid][2] = c2; }
    __syncthreads();
    if (tid < 3) {
        int s = 0;
        for (int q = 0; q < K2_WARPS; q++) s += swarp[q][tid];
        stot[tid] = s;
    }
    __syncthreads();

    int S;
    if (stot[0] >= need && stot[0] <= CAP) {
        S = stot[0];                               // common path: capture already done
    } else {
        unsigned T;
        if (stot[1] >= need && stot[1] <= CAP)      { T = T1; S = stot[1]; }
        else if (stot[2] <= CAP)                    { T = 1u; S = stot[2]; }
        else {
            // exactness backstop: binary-search tightest threshold in [need, CAP]
            if (tid == 0) {
                if (stot[1] >= need) { sLo = (int)T1; sHi = (int)T0; sT = T1; sS = stot[1]; }
                else                 { sLo = (int)1u; sHi = (int)T1; sT = 1u; sS = stot[2]; }
                sFlag = 1;
            }
            __syncthreads();
            for (int iter = 0; iter < 34 && sFlag; iter++) {
                unsigned lo = (unsigned)sLo, hi = (unsigned)sHi;
                if (hi - lo <= 1u) break;
                unsigned mid = lo + ((hi - lo) >> 1);
                int c = 0;
                for (int i = tid; i < L; i += K2_THREADS) c += (LD(i).x >= mid);
#pragma unroll
                for (int o = 16; o > 0; o >>= 1) c += __shfl_down_sync(0xffffffffu, c, o);
                if (lane == 0) swarp[wid][0] = c;
                __syncthreads();
                if (tid == 0) {
                    int s = 0;
                    for (int q = 0; q < K2_WARPS; q++) s += swarp[q][0];
                    if (s >= need) { sLo = (int)mid; sT = mid; sS = s; }
                    else           { sHi = (int)mid; }
                    if (sS <= CAP) sFlag = 0;
                }
                __syncthreads();
            }
            __syncthreads();
            T = sT; S = min(sS, CAP);
        }
        // recapture at T (rare path)
        if (tid == 0) scap = 0;
        __syncthreads();
        for (int i = tid; i < L; i += K2_THREADS) {
            uint2 e = LD(i);
            if (e.x >= T) { int p = atomicAdd(&scap, 1); if (p < CAP) ss[p] = e; }
        }
        __syncthreads();
    }
    if (tid == 0) { s_sel = 0u; s_needr = need; s_tiecnt = 0; }
    __syncthreads();

    // ---- radix select: exact k-th largest value among S captured ----
#pragma unroll 1
    for (int p = 0; p < 4; p++) {
        int shift = 24 - 8 * p;
        if (tid < 256) hist[tid] = 0;
        __syncthreads();
        unsigned selhi = s_sel;
        int nr = s_needr;
        for (int j = tid; j < S; j += K2_THREADS) {
            unsigned v = ss[j].x;
            if (p == 0 || (v >> (shift + 8)) == (selhi >> (shift + 8)))
                atomicAdd(&hist[(v >> shift) & 0xFFu], 1);
        }
        __syncthreads();
        if (wid == 0 && nr > 0) {
            int bbase = 255 - 8 * lane;            // lane covers 8 bins, descending
            int ch = 0;
#pragma unroll
            for (int q = 0; q < 8; q++) ch += hist[bbase - q];
            int pre = ch;
#pragma unroll
            for (int o = 1; o < 32; o <<= 1) {
                int v = __shfl_up_sync(0xffffffffu, pre, o);
                if (lane >= o) pre += v;
            }
            int excl = pre - ch;
            if (excl < nr && nr <= pre) {
                int tgt = nr - excl, cum = 0;
                for (int q = 0; q < 8; q++) {
                    int c = hist[bbase - q];
                    if (cum + c >= tgt) {
                        s_sel = selhi | ((unsigned)(bbase - q) << shift);
                        s_needr = tgt - cum;
                        break;
                    }
                    cum += c;
                }
            }
        }
        __syncthreads();
    }
    unsigned Tk = s_sel;
    int r = s_needr;                               // ties at boundary to take

    // ---- gather boundary ties, sort by anchor index (lowest first) ----
    for (int j = tid; j < S; j += K2_THREADS) {
        if (ss[j].x == Tk) {
            int p = atomicAdd(&s_tiecnt, 1);
            if (p < TIE_CAP) stie[p] = ss[j].y;
        }
    }
    __syncthreads();
    if (tid == 0 && need > 0) {
        int c = min(s_tiecnt, TIE_CAP);
        for (int i = 1; i < c; i++) {              // insertion sort by a = y & 0x1FFFF
            unsigned key = stie[i]; int j = i - 1;
            while (j >= 0 && (stie[j] & 0x1FFFFu) > (key & 0x1FFFFu)) {
                stie[j + 1] = stie[j]; j--;
            }
            stie[j + 1] = key;
        }
    }
    __syncthreads();

    // ---- order-free accumulation: all v > Tk, plus first r ties ----
    float b = 0.0f, p = 0.0f, l = 0.0f;
    if (need > 0) {
        for (int j = tid; j < S; j += K2_THREADS) {
            uint2 e = ss[j];
            if (e.x > Tk) {
                int a = (int)(e.y & 0x1FFFFu);
                if (cat) {
                    float x = cls[cls_index(n, a)];
                    b += softplusf(x); p += x;
                } else {
                    int m = (int)(e.y >> 17);
                    pos_contrib(cls, deltas, gt, n, a, m, b, p, l);
                }
            }
        }
        if (tid < r) {
            unsigned y = stie[tid];
            int a = (int)(y & 0x1FFFFu);
            if (cat) {
                float x = cls[cls_index(n, a)];
                b += softplusf(x); p += x;
            } else {
                int m = (int)(y >> 17);
                pos_contrib(cls, deltas, gt, n, a, m, b, p, l);
            }
        }
    }
#pragma unroll
    for (int o = 16; o > 0; o >>= 1) {
        b += __shfl_down_sync(0xffffffffu, b, o);
        p += __shfl_down_sync(0xffffffffu, p, o);
        l += __shfl_down_sync(0xffffffffu, l, o);
    }
    if (lane == 0) { fwarp[wid][0] = b; fwarp[wid][1] = p; fwarp[wid][2] = l; }
    __syncthreads();

    if (tid == 0) {
        float sb = 0.f, sp = 0.f, sl_ = 0.f;
        for (int q = 0; q < K2_WARPS; q++) {
            sb += fwarp[q][0]; sp += fwarp[q][1]; sl_ += fwarp[q][2];
        }
        g_part[n][cat] = make_float4(sb, sp, sl_, (float)need);
        __threadfence();
        int ticket = atomicAdd(&g_ticket, 1);
        if (ticket == N_IMG * 2 - 1) {
            __threadfence();
            float cl = 0.f, bl = 0.f, fg = 0.f, bg = 0.f, pm = 0.f;
            for (int q = 0; q < N_IMG; q++) {
                volatile float* Pp = (volatile float*)&g_part[q][0];
                volatile float* Gg = (volatile float*)&g_part[q][1];
                float Pb = Pp[0], Pd = Pp[1], Pl = Pp[2], np = Pp[3];
                float Gb = Gg[0], Gd = Gg[1], nn = Gg[3];
                float denom = fmaxf(np + nn, 1.0f);
                cl += (Pb + Gb) / denom;
                bl += Pl / (fmaxf(np, 1.0f) * (float)N_IMG);
                fg += np; bg += nn;
                if (q == N_IMG - 1) pm = (Pd + Gd) / denom;
            }
            out[0] = cl; out[1] = bl; out[2] = bg; out[3] = fg; out[4] = pm;
            for (int i = 5; i < out_size; i++) out[i] = 0.0f;
            g_ticket = 0;
        }
    }
}

// ---------------- host launcher ----------------
extern "C" void kernel_launch(void* const* d_in, const int* in_sizes, int n_in,
                              void* d_out, int out_size) {
    (void)in_sizes; (void)n_in;
    const float* cls    = (const float*)d_in[0];
    const float* deltas = (const float*)d_in[1];
    const float* gt     = (const float*)d_in[2];
    float* out = (float*)d_out;

    Keys keys;
    for (int n = 0; n < N_IMG; n++) {
        unsigned K0, K1;
        tf2x32(0u, 42u, 0u, (unsigned)n, K0, K1);
        unsigned p0, p1, q0, q1;
        tf2x32(K0, K1, 0u, 0u, p0, p1);
        tf2x32(K0, K1, 0u, 1u, q0, q1);
        keys.kp0[n] = p0; keys.kp1[n] = p1;
        keys.kn0[n] = q0; keys.kn1[n] = q1;
    }

    cudaMemcpyToSymbolAsync(c_gt, gt, N_IMG * M_GT * sizeof(float4), 0,
                            cudaMemcpyDeviceToDevice, 0);

    dim3 g1(A_ANCH / K1_THREADS, N_IMG);                   // 405 x 8
    k_match<<<g1, K1_THREADS>>>(deltas, keys);
    k_select<<<N_IMG * 2, K2_THREADS>>>(cls, deltas, gt, out, out_size);
}